// round 8
// baseline (speedup 1.0000x reference)
#include <cuda_runtime.h>

// Problem constants
#define B_ 4
#define S_ 1024
#define D_ 768
#define H_ 12
#define E_ 64

// ---------------------------------------------------------------------------
// Device scratch (static __device__ arrays: the sanctioned no-alloc workaround)
// ---------------------------------------------------------------------------
__device__ __align__(16) float g_q[B_ * H_ * S_ * E_];    // 12 MB
__device__ __align__(16) float g_k[B_ * H_ * S_ * E_];    // 12 MB
__device__ __align__(16) float g_v[B_ * H_ * S_ * E_];    // 12 MB
__device__ __align__(16) float g_attn[(size_t)B_ * H_ * S_ * S_]; // 201 MB (logits, reused in-place for probs)
__device__ __align__(16) float g_ctx[B_ * S_ * D_];       // 12 MB

// ---------------------------------------------------------------------------
// SGEMM tile config: 128x64 CTA tile, BK=16, 256 threads, 8x4 per thread
// ---------------------------------------------------------------------------
#define GBM 128
#define GBN 64
#define GBK 16

// C[m0:m0+128, n0:n0+64] += A[M,K] * B[N,K]^T   (both row-major, NT)
__device__ __forceinline__ void mm_nt(const float* __restrict__ A, int lda,
                                      const float* __restrict__ B, int ldb,
                                      int K, int m0, int n0,
                                      float* As, float* Bs, float acc[8][4])
{
    const int tid = threadIdx.x;
    const int ty = tid >> 4, tx = tid & 15;
    for (int k0 = 0; k0 < K; k0 += GBK) {
        // A tile: 128x16 -> As[k][m] (transposed store)
#pragma unroll
        for (int it = 0; it < 2; ++it) {
            int i4 = tid + it * 256;
            int row = i4 >> 2;
            int c = (i4 & 3) << 2;
            const float4 va = *(const float4*)(A + (size_t)(m0 + row) * lda + k0 + c);
            As[(c + 0) * GBM + row] = va.x;
            As[(c + 1) * GBM + row] = va.y;
            As[(c + 2) * GBM + row] = va.z;
            As[(c + 3) * GBM + row] = va.w;
        }
        // B tile (NT): 64x16 -> Bs[k][n]
        {
            int row = tid >> 2;
            int c = (tid & 3) << 2;
            const float4 vb = *(const float4*)(B + (size_t)(n0 + row) * ldb + k0 + c);
            Bs[(c + 0) * GBN + row] = vb.x;
            Bs[(c + 1) * GBN + row] = vb.y;
            Bs[(c + 2) * GBN + row] = vb.z;
            Bs[(c + 3) * GBN + row] = vb.w;
        }
        __syncthreads();
#pragma unroll
        for (int kk = 0; kk < GBK; ++kk) {
            float ar[8], br[4];
#pragma unroll
            for (int i = 0; i < 8; ++i) ar[i] = As[kk * GBM + ty * 8 + i];
#pragma unroll
            for (int j = 0; j < 4; ++j) br[j] = Bs[kk * GBN + tx * 4 + j];
#pragma unroll
            for (int i = 0; i < 8; ++i)
#pragma unroll
                for (int j = 0; j < 4; ++j)
                    acc[i][j] = fmaf(ar[i], br[j], acc[i][j]);
        }
        __syncthreads();
    }
}

// C[m0:m0+128, n0:n0+64] += A[M,K] * B[K,N]   (row-major, NN)
__device__ __forceinline__ void mm_nn(const float* __restrict__ A, int lda,
                                      const float* __restrict__ B, int ldb,
                                      int K, int m0, int n0,
                                      float* As, float* Bs, float acc[8][4])
{
    const int tid = threadIdx.x;
    const int ty = tid >> 4, tx = tid & 15;
    for (int k0 = 0; k0 < K; k0 += GBK) {
#pragma unroll
        for (int it = 0; it < 2; ++it) {
            int i4 = tid + it * 256;
            int row = i4 >> 2;
            int c = (i4 & 3) << 2;
            const float4 va = *(const float4*)(A + (size_t)(m0 + row) * lda + k0 + c);
            As[(c + 0) * GBM + row] = va.x;
            As[(c + 1) * GBM + row] = va.y;
            As[(c + 2) * GBM + row] = va.z;
            As[(c + 3) * GBM + row] = va.w;
        }
        // B tile (NN): rows are k, contiguous in n -> direct float4 copy
        {
            int kk = tid >> 4;            // 0..15
            int c = (tid & 15) << 2;      // 0..60
            const float4 vb = *(const float4*)(B + (size_t)(k0 + kk) * ldb + n0 + c);
            *(float4*)(Bs + kk * GBN + c) = vb;
        }
        __syncthreads();
#pragma unroll
        for (int kk = 0; kk < GBK; ++kk) {
            float ar[8], br[4];
#pragma unroll
            for (int i = 0; i < 8; ++i) ar[i] = As[kk * GBM + ty * 8 + i];
#pragma unroll
            for (int j = 0; j < 4; ++j) br[j] = Bs[kk * GBN + tx * 4 + j];
#pragma unroll
            for (int i = 0; i < 8; ++i)
#pragma unroll
                for (int j = 0; j < 4; ++j)
                    acc[i][j] = fmaf(ar[i], br[j], acc[i][j]);
        }
        __syncthreads();
    }
}

// ---------------------------------------------------------------------------
// K1: QKV projection. C[4096,2304] = x[4096,768] * Wqkv[2304,768]^T,
//     scattered into g_q/g_k/g_v in [B,H,S,E] layout.
// ---------------------------------------------------------------------------
__global__ void __launch_bounds__(256) k_qkv(const float* __restrict__ x,
                                             const float* __restrict__ Wqkv)
{
    __shared__ __align__(16) float As[GBK * GBM];
    __shared__ __align__(16) float Bs[GBK * GBN];
    float acc[8][4] = {};
    const int m0 = blockIdx.y * GBM;
    const int n0 = blockIdx.x * GBN;
    mm_nt(x, D_, Wqkv, D_, D_, m0, n0, As, Bs, acc);

    const int ty = threadIdx.x >> 4, tx = threadIdx.x & 15;
    // n0 is a multiple of 64 -> the 64-wide tile sits entirely inside one (t,h)
    const int t = n0 / D_;            // 0=q, 1=k, 2=v
    const int h = (n0 % D_) / E_;
    float* dst = (t == 0) ? g_q : (t == 1) ? g_k : g_v;
    const int e0 = tx * 4;
#pragma unroll
    for (int i = 0; i < 8; ++i) {
        const int m = m0 + ty * 8 + i;
        const int b = m >> 10, s = m & 1023;
        *(float4*)(dst + (((size_t)(b * H_ + h)) * S_ + s) * E_ + e0) =
            make_float4(acc[i][0], acc[i][1], acc[i][2], acc[i][3]);
    }
}

// ---------------------------------------------------------------------------
// K2: logits = Q K^T per (b,h). 48 batches of 1024x1024x64 (NT).
// ---------------------------------------------------------------------------
__global__ void __launch_bounds__(256) k_qk()
{
    __shared__ __align__(16) float As[GBK * GBM];
    __shared__ __align__(16) float Bs[GBK * GBN];
    float acc[8][4] = {};
    const int bh = blockIdx.z;
    const float* Q = g_q + (size_t)bh * S_ * E_;
    const float* Kp = g_k + (size_t)bh * S_ * E_;
    const int m0 = blockIdx.y * GBM;
    const int n0 = blockIdx.x * GBN;
    mm_nt(Q, E_, Kp, E_, E_, m0, n0, As, Bs, acc);

    float* C = g_attn + (size_t)bh * S_ * S_;
    const int ty = threadIdx.x >> 4, tx = threadIdx.x & 15;
#pragma unroll
    for (int i = 0; i < 8; ++i) {
        *(float4*)(C + (size_t)(m0 + ty * 8 + i) * S_ + n0 + tx * 4) =
            make_float4(acc[i][0], acc[i][1], acc[i][2], acc[i][3]);
    }
}

// ---------------------------------------------------------------------------
// K3: talking-heads mix1 -> softmax -> mix2, one CTA per (b,q), in place.
//     exp via FFMA-pipe polynomial to avoid the MUFU throughput ceiling.
// ---------------------------------------------------------------------------
__device__ __forceinline__ float fast_exp(float x)
{
    // exp(x) = 2^(x*log2e); x <= 0 in softmax (max subtracted)
    const float y = x * 1.4426950408889634f;
    const float r = rintf(y);
    const float f = y - r;
    float p = 1.5403530e-4f;
    p = fmaf(p, f, 1.3333558e-3f);
    p = fmaf(p, f, 9.6181291e-3f);
    p = fmaf(p, f, 5.5504109e-2f);
    p = fmaf(p, f, 2.4022651e-1f);
    p = fmaf(p, f, 6.9314718e-1f);
    p = fmaf(p, f, 1.0f);
    const int ri = (int)fmaxf(r, -126.0f);  // clamp: underflow -> ~0, no wrap
    return __int_as_float(__float_as_int(p) + (ri << 23));
}

__global__ void __launch_bounds__(256) k_mix_softmax(const float* __restrict__ Wl,
                                                     const float* __restrict__ bl,
                                                     const float* __restrict__ Ww,
                                                     const float* __restrict__ bw)
{
    extern __shared__ __align__(16) float sm[];
    float* rowbuf = sm;                 // [12][1024]
    float* wWl = sm + H_ * S_;          // 144
    float* wbl = wWl + 144;             // 12
    float* wWw = wbl + 12;              // 144
    float* wbw = wWw + 144;             // 12

    const int tid = threadIdx.x;
    const int bq = blockIdx.x;
    const int b = bq >> 10, q = bq & 1023;

    for (int i = tid; i < 144; i += 256) { wWl[i] = Wl[i]; wWw[i] = Ww[i]; }
    if (tid < 12) { wbl[tid] = bl[tid]; wbw[tid] = bw[tid]; }

    // Load the 12 head rows A[b,h,q,:] into smem
    const size_t base = ((size_t)b * H_) * S_ * S_ + (size_t)q * S_;
    for (int h = 0; h < H_; ++h) {
        const float4* src = (const float4*)(g_attn + base + (size_t)h * S_ * S_);
        float4* dst = (float4*)(rowbuf + h * S_);
        dst[tid] = src[tid];  // 256 float4 = 1024 floats
    }
    __syncthreads();

    // mix1 per column: m[g] = bl[g] + sum_h Wl[g,h] * l[h]
    for (int k = tid; k < S_; k += 256) {
        float l[H_];
#pragma unroll
        for (int h = 0; h < H_; ++h) l[h] = rowbuf[h * S_ + k];
        float m[H_];
#pragma unroll
        for (int g = 0; g < H_; ++g) {
            float a = wbl[g];
#pragma unroll
            for (int h = 0; h < H_; ++h) a = fmaf(wWl[g * H_ + h], l[h], a);
            m[g] = a;
        }
#pragma unroll
        for (int g = 0; g < H_; ++g) rowbuf[g * S_ + k] = m[g];
    }
    __syncthreads();

    // softmax per row, warp-per-row
    const int warp = tid >> 5, lane = tid & 31;
    for (int row = warp; row < H_; row += 8) {
        float* r = rowbuf + row * S_;
        float mx = -1e30f;
        for (int k = lane; k < S_; k += 32) mx = fmaxf(mx, r[k]);
#pragma unroll
        for (int o = 16; o; o >>= 1) mx = fmaxf(mx, __shfl_xor_sync(0xffffffffu, mx, o));
        float s = 0.f;
        for (int k = lane; k < S_; k += 32) {
            const float e = fast_exp(r[k] - mx);
            r[k] = e;
            s += e;
        }
#pragma unroll
        for (int o = 16; o; o >>= 1) s += __shfl_xor_sync(0xffffffffu, s, o);
        const float inv = 1.0f / s;
        for (int k = lane; k < S_; k += 32) r[k] *= inv;
    }
    __syncthreads();

    // mix2 per column, write back to global (in place; this CTA owns its rows)
    for (int k = tid; k < S_; k += 256) {
        float pr[H_];
#pragma unroll
        for (int h = 0; h < H_; ++h) pr[h] = rowbuf[h * S_ + k];
#pragma unroll
        for (int g = 0; g < H_; ++g) {
            float a = wbw[g];
#pragma unroll
            for (int h = 0; h < H_; ++h) a = fmaf(wWw[g * H_ + h], pr[h], a);
            g_attn[base + (size_t)g * S_ * S_ + k] = a;
        }
    }
}

// ---------------------------------------------------------------------------
// K4: O = P V per (b,h). 48 batches of 1024x64x1024 (NN), writes ctx [B,S,D].
// ---------------------------------------------------------------------------
__global__ void __launch_bounds__(256) k_av()
{
    __shared__ __align__(16) float As[GBK * GBM];
    __shared__ __align__(16) float Bs[GBK * GBN];
    float acc[8][4] = {};
    const int bh = blockIdx.z;
    const float* P = g_attn + (size_t)bh * S_ * S_;
    const float* V = g_v + (size_t)bh * S_ * E_;
    const int m0 = blockIdx.y * GBM;
    mm_nn(P, S_, V, E_, S_, m0, 0, As, Bs, acc);

    const int b = bh / H_, h = bh % H_;
    const int ty = threadIdx.x >> 4, tx = threadIdx.x & 15;
#pragma unroll
    for (int i = 0; i < 8; ++i) {
        const int q = m0 + ty * 8 + i;
        *(float4*)(g_ctx + ((size_t)(b * S_ + q)) * D_ + h * E_ + tx * 4) =
            make_float4(acc[i][0], acc[i][1], acc[i][2], acc[i][3]);
    }
}

// ---------------------------------------------------------------------------
// K5: out = ctx Wp^T + bp. 4096x768x768 (NT).
// ---------------------------------------------------------------------------
__global__ void __launch_bounds__(256) k_proj(const float* __restrict__ Wp,
                                              const float* __restrict__ bp,
                                              float* __restrict__ out)
{
    __shared__ __align__(16) float As[GBK * GBM];
    __shared__ __align__(16) float Bs[GBK * GBN];
    float acc[8][4] = {};
    const int m0 = blockIdx.y * GBM;
    const int n0 = blockIdx.x * GBN;
    mm_nt(g_ctx, D_, Wp, D_, D_, m0, n0, As, Bs, acc);

    const int ty = threadIdx.x >> 4, tx = threadIdx.x & 15;
    const float4 bias = *(const float4*)(bp + n0 + tx * 4);
#pragma unroll
    for (int i = 0; i < 8; ++i) {
        const int m = m0 + ty * 8 + i;
        *(float4*)(out + (size_t)m * D_ + n0 + tx * 4) =
            make_float4(acc[i][0] + bias.x, acc[i][1] + bias.y,
                        acc[i][2] + bias.z, acc[i][3] + bias.w);
    }
}

// ---------------------------------------------------------------------------
// Launch
// ---------------------------------------------------------------------------
extern "C" void kernel_launch(void* const* d_in, const int* in_sizes, int n_in,
                              void* d_out, int out_size)
{
    const float* x    = (const float*)d_in[0];
    const float* Wqkv = (const float*)d_in[1];
    const float* Wl   = (const float*)d_in[2];
    const float* bl   = (const float*)d_in[3];
    const float* Ww   = (const float*)d_in[4];
    const float* bw   = (const float*)d_in[5];
    const float* Wp   = (const float*)d_in[6];
    const float* bp   = (const float*)d_in[7];
    float* out = (float*)d_out;

    // 12*1024 row floats + 312 weight floats
    const int mix_smem = (H_ * S_ + 320) * (int)sizeof(float);
    cudaFuncSetAttribute(k_mix_softmax, cudaFuncAttributeMaxDynamicSharedMemorySize,
                         mix_smem);

    k_qkv<<<dim3(3 * D_ / GBN, (B_ * S_) / GBM), 256>>>(x, Wqkv);
    k_qk<<<dim3(S_ / GBN, S_ / GBM, B_ * H_), 256>>>();
    k_mix_softmax<<<B_ * S_, 256, mix_smem>>>(Wl, bl, Ww, bw);
    k_av<<<dim3(1, S_ / GBM, B_ * H_), 256>>>();
    k_proj<<<dim3(D_ / GBN, (B_ * S_) / GBM), 256>>>(Wp, bp, out);
}

// round 10
// speedup vs baseline: 1.8139x; 1.8139x over previous
#include <cuda_runtime.h>
#include <cuda_bf16.h>
#include <cstdint>

#define B_ 4
#define S_ 1024
#define D_ 768
#define H_ 12
#define E_ 64

__device__ __align__(16) float g_q[B_ * H_ * S_ * E_];
__device__ __align__(16) float g_k[B_ * H_ * S_ * E_];
__device__ __align__(16) float g_v[B_ * H_ * S_ * E_];
__device__ __align__(16) float g_attn[(size_t)B_ * H_ * S_ * S_];
__device__ __align__(16) float g_ctx[B_ * S_ * D_];

// Word pitch (uint32 = bf16x2) per tile row: 12 -> (g*12+tg) mod 32 covers all
// 32 banks for g in 0..7, tg in 0..3 (fragment LDS is conflict-free).
#define PW 12

// Split fp32 pair into packed bf16x2 hi and lo words (lo = exact residual).
__device__ __forceinline__ void bsplit(float a, float b, uint32_t& hi, uint32_t& lo)
{
    __nv_bfloat162 h = __floats2bfloat162_rn(a, b);
    const float ha = __bfloat162float(h.x), hb = __bfloat162float(h.y);
    __nv_bfloat162 l = __floats2bfloat162_rn(a - ha, b - hb);
    hi = *reinterpret_cast<uint32_t*>(&h);
    lo = *reinterpret_cast<uint32_t*>(&l);
}

__device__ __forceinline__ void mma_bf16(float c[4], const uint32_t a[4],
                                         const uint32_t b[2])
{
    asm volatile(
        "mma.sync.aligned.m16n8k16.row.col.f32.bf16.bf16.f32 "
        "{%0,%1,%2,%3}, {%4,%5,%6,%7}, {%8,%9}, {%0,%1,%2,%3};\n"
        : "+f"(c[0]), "+f"(c[1]), "+f"(c[2]), "+f"(c[3])
        : "r"(a[0]), "r"(a[1]), "r"(a[2]), "r"(a[3]), "r"(b[0]), "r"(b[1]));
}

// ---------------------------------------------------------------------------
// Split-bf16 GEMM core (3 MMAs per fragment: hh + hl + lh), BK=16, dbl-buffered
//   C[m0:m0+BM, n0:n0+BN] += A[M,K] * op(B)
//   BTRANS=false: B row-major [N,K] (NT) ; BTRANS=true: B row-major [K,N] (NN)
// ---------------------------------------------------------------------------
template<int BM, int BN, int THREADS, int WARPS_M, int MT, int NTT, bool BTRANS>
__device__ __forceinline__ void gemm_b3(
    const float* __restrict__ A, int lda,
    const float* __restrict__ Bg, int ldb,
    int K, int m0, int n0,
    uint32_t* Ah, uint32_t* Al, uint32_t* Bh, uint32_t* Bl,
    float acc[MT][NTT][4])
{
    const int tid = threadIdx.x;
    const int warp = tid >> 5, lane = tid & 31;
    const int wm0 = (warp % WARPS_M) * (MT * 16);
    const int wn0 = (warp / WARPS_M) * (NTT * 8);
    const int g = lane >> 2, tg = lane & 3;

    constexpr int AIT = (BM * 4) / THREADS;                  // float4 / thread
    constexpr int BIT_NT = BTRANS ? 1 : (BN * 4) / THREADS;

    float4 a_reg[AIT];
    float  b_reg[BTRANS ? 4 : 4 * BIT_NT];

    auto ldg_tiles = [&](int k0) {
#pragma unroll
        for (int i = 0; i < AIT; ++i) {
            int idx = tid + i * THREADS;
            int row = idx >> 2, c = (idx & 3) << 2;
            a_reg[i] = *(const float4*)(A + (size_t)(m0 + row) * lda + k0 + c);
        }
        if (!BTRANS) {
#pragma unroll
            for (int i = 0; i < BIT_NT; ++i) {
                int idx = tid + i * THREADS;
                int row = idx >> 2, c = (idx & 3) << 2;
                const float4 v =
                    *(const float4*)(Bg + (size_t)(n0 + row) * ldb + k0 + c);
                b_reg[i * 4 + 0] = v.x; b_reg[i * 4 + 1] = v.y;
                b_reg[i * 4 + 2] = v.z; b_reg[i * 4 + 3] = v.w;
            }
        } else {
            const int n = tid & (BN - 1);
            const int kq = (tid / BN) * 4;
#pragma unroll
            for (int j = 0; j < 4; ++j)
                b_reg[j] = Bg[(size_t)(k0 + kq + j) * ldb + n0 + n];
        }
    };

    auto sts_tiles = [&](int buf) {
        uint32_t* Ahd = Ah + buf * (BM * PW);
        uint32_t* Ald = Al + buf * (BM * PW);
        uint32_t* Bhd = Bh + buf * (BN * PW);
        uint32_t* Bld = Bl + buf * (BN * PW);
#pragma unroll
        for (int i = 0; i < AIT; ++i) {
            int idx = tid + i * THREADS;
            int row = idx >> 2, w = (idx & 3) << 1;   // word offset = c/2
            uint32_t h0, l0, h1, l1;
            bsplit(a_reg[i].x, a_reg[i].y, h0, l0);
            bsplit(a_reg[i].z, a_reg[i].w, h1, l1);
            *(uint2*)(Ahd + row * PW + w) = make_uint2(h0, h1);
            *(uint2*)(Ald + row * PW + w) = make_uint2(l0, l1);
        }
        if (!BTRANS) {
#pragma unroll
            for (int i = 0; i < BIT_NT; ++i) {
                int idx = tid + i * THREADS;
                int row = idx >> 2, w = (idx & 3) << 1;
                uint32_t h0, l0, h1, l1;
                bsplit(b_reg[i * 4 + 0], b_reg[i * 4 + 1], h0, l0);
                bsplit(b_reg[i * 4 + 2], b_reg[i * 4 + 3], h1, l1);
                *(uint2*)(Bhd + row * PW + w) = make_uint2(h0, h1);
                *(uint2*)(Bld + row * PW + w) = make_uint2(l0, l1);
            }
        } else {
            const int n = tid & (BN - 1);
            const int w = ((tid / BN) * 4) >> 1;   // kq/2
            uint32_t h0, l0, h1, l1;
            bsplit(b_reg[0], b_reg[1], h0, l0);
            bsplit(b_reg[2], b_reg[3], h1, l1);
            *(uint2*)(Bhd + n * PW + w) = make_uint2(h0, h1);
            *(uint2*)(Bld + n * PW + w) = make_uint2(l0, l1);
        }
    };

    auto compute = [&](int buf) {
        const uint32_t* Ahd = Ah + buf * (BM * PW);
        const uint32_t* Ald = Al + buf * (BM * PW);
        const uint32_t* Bhd = Bh + buf * (BN * PW);
        const uint32_t* Bld = Bl + buf * (BN * PW);
        uint32_t bh[NTT][2], bl[NTT][2];
#pragma unroll
        for (int nt = 0; nt < NTT; ++nt) {
            const uint32_t* q = Bhd + (wn0 + nt * 8 + g) * PW + tg;
            bh[nt][0] = q[0]; bh[nt][1] = q[4];
            const uint32_t* ql = Bld + (wn0 + nt * 8 + g) * PW + tg;
            bl[nt][0] = ql[0]; bl[nt][1] = ql[4];
        }
#pragma unroll
        for (int mt = 0; mt < MT; ++mt) {
            uint32_t ah[4], al[4];
            const uint32_t* p = Ahd + (wm0 + mt * 16 + g) * PW + tg;
            ah[0] = p[0]; ah[1] = p[8 * PW]; ah[2] = p[4]; ah[3] = p[8 * PW + 4];
            const uint32_t* pl = Ald + (wm0 + mt * 16 + g) * PW + tg;
            al[0] = pl[0]; al[1] = pl[8 * PW]; al[2] = pl[4]; al[3] = pl[8 * PW + 4];
#pragma unroll
            for (int nt = 0; nt < NTT; ++nt) {
                mma_bf16(acc[mt][nt], ah, bh[nt]);
                mma_bf16(acc[mt][nt], ah, bl[nt]);
                mma_bf16(acc[mt][nt], al, bh[nt]);
            }
        }
    };

    ldg_tiles(0);
    sts_tiles(0);
    __syncthreads();
    const int nkt = K / 16;
    for (int kt = 0; kt < nkt; ++kt) {
        if (kt + 1 < nkt) ldg_tiles((kt + 1) * 16);
        compute(kt & 1);
        if (kt + 1 < nkt) sts_tiles((kt + 1) & 1);
        __syncthreads();
    }
}

#define CFGA 128, 128, 256, 4, 2, 8
#define CFGB 128, 64, 256, 8, 1, 8

// ---------------------------------------------------------------------------
// K1: QKV projection [4096,2304] = x * Wqkv^T, scattered to q/k/v [B,H,S,E]
// ---------------------------------------------------------------------------
__global__ void __launch_bounds__(256) k_qkv(const float* __restrict__ x,
                                             const float* __restrict__ Wqkv)
{
    __shared__ __align__(16) uint32_t Ah[2 * 128 * PW], Al[2 * 128 * PW];
    __shared__ __align__(16) uint32_t Bh[2 * 128 * PW], Bl[2 * 128 * PW];
    float acc[2][8][4] = {};
    const int m0 = blockIdx.y * 128;
    const int n0 = blockIdx.x * 128;
    gemm_b3<CFGA, false>(x, D_, Wqkv, D_, D_, m0, n0, Ah, Al, Bh, Bl, acc);

    const int tid = threadIdx.x;
    const int warp = tid >> 5, lane = tid & 31;
    const int wm0 = (warp % 4) * 32, wn0 = (warp / 4) * 64;
    const int g = lane >> 2, tg = lane & 3;
#pragma unroll
    for (int mt = 0; mt < 2; ++mt)
#pragma unroll
        for (int nt = 0; nt < 8; ++nt) {
            const int n = n0 + wn0 + nt * 8 + 2 * tg;
            const int t = n / D_;
            const int h = (n % D_) / E_;
            const int e = n % E_;
            float* dst = (t == 0) ? g_q : (t == 1) ? g_k : g_v;
#pragma unroll
            for (int half = 0; half < 2; ++half) {
                const int m = m0 + wm0 + mt * 16 + g + half * 8;
                const int b = m >> 10, s = m & 1023;
                *(float2*)(dst + (((size_t)(b * H_ + h)) * S_ + s) * E_ + e) =
                    make_float2(acc[mt][nt][half * 2], acc[mt][nt][half * 2 + 1]);
            }
        }
}

// ---------------------------------------------------------------------------
// K2: logits = Q K^T per (b,h). 48 batches of 1024x1024x64 (NT).
// ---------------------------------------------------------------------------
__global__ void __launch_bounds__(256) k_qk()
{
    __shared__ __align__(16) uint32_t Ah[2 * 128 * PW], Al[2 * 128 * PW];
    __shared__ __align__(16) uint32_t Bh[2 * 128 * PW], Bl[2 * 128 * PW];
    float acc[2][8][4] = {};
    const int bh = blockIdx.z;
    const float* Q = g_q + (size_t)bh * S_ * E_;
    const float* Kp = g_k + (size_t)bh * S_ * E_;
    const int m0 = blockIdx.y * 128;
    const int n0 = blockIdx.x * 128;
    gemm_b3<CFGA, false>(Q, E_, Kp, E_, E_, m0, n0, Ah, Al, Bh, Bl, acc);

    float* C = g_attn + (size_t)bh * S_ * S_;
    const int tid = threadIdx.x;
    const int warp = tid >> 5, lane = tid & 31;
    const int wm0 = (warp % 4) * 32, wn0 = (warp / 4) * 64;
    const int g = lane >> 2, tg = lane & 3;
#pragma unroll
    for (int mt = 0; mt < 2; ++mt)
#pragma unroll
        for (int nt = 0; nt < 8; ++nt) {
            const int n = n0 + wn0 + nt * 8 + 2 * tg;
#pragma unroll
            for (int half = 0; half < 2; ++half) {
                const int m = m0 + wm0 + mt * 16 + g + half * 8;
                *(float2*)(C + (size_t)m * S_ + n) =
                    make_float2(acc[mt][nt][half * 2], acc[mt][nt][half * 2 + 1]);
            }
        }
}

// ---------------------------------------------------------------------------
// K3: talking-heads mix1 -> softmax -> mix2 (unchanged; known-good fp32)
// ---------------------------------------------------------------------------
__device__ __forceinline__ float fast_exp(float x)
{
    const float y = x * 1.4426950408889634f;
    const float r = rintf(y);
    const float f = y - r;
    float p = 1.5403530e-4f;
    p = fmaf(p, f, 1.3333558e-3f);
    p = fmaf(p, f, 9.6181291e-3f);
    p = fmaf(p, f, 5.5504109e-2f);
    p = fmaf(p, f, 2.4022651e-1f);
    p = fmaf(p, f, 6.9314718e-1f);
    p = fmaf(p, f, 1.0f);
    const int ri = (int)fmaxf(r, -126.0f);
    return __int_as_float(__float_as_int(p) + (ri << 23));
}

__global__ void __launch_bounds__(256) k_mix_softmax(const float* __restrict__ Wl,
                                                     const float* __restrict__ bl,
                                                     const float* __restrict__ Ww,
                                                     const float* __restrict__ bw)
{
    extern __shared__ __align__(16) float sm[];
    float* rowbuf = sm;
    float* wWl = sm + H_ * S_;
    float* wbl = wWl + 144;
    float* wWw = wbl + 12;
    float* wbw = wWw + 144;

    const int tid = threadIdx.x;
    const int bq = blockIdx.x;
    const int b = bq >> 10, q = bq & 1023;

    for (int i = tid; i < 144; i += 256) { wWl[i] = Wl[i]; wWw[i] = Ww[i]; }
    if (tid < 12) { wbl[tid] = bl[tid]; wbw[tid] = bw[tid]; }

    const size_t base = ((size_t)b * H_) * S_ * S_ + (size_t)q * S_;
    for (int h = 0; h < H_; ++h) {
        const float4* src = (const float4*)(g_attn + base + (size_t)h * S_ * S_);
        float4* dst = (float4*)(rowbuf + h * S_);
        dst[tid] = src[tid];
    }
    __syncthreads();

    for (int k = tid; k < S_; k += 256) {
        float l[H_];
#pragma unroll
        for (int h = 0; h < H_; ++h) l[h] = rowbuf[h * S_ + k];
        float m[H_];
#pragma unroll
        for (int g = 0; g < H_; ++g) {
            float a = wbl[g];
#pragma unroll
            for (int h = 0; h < H_; ++h) a = fmaf(wWl[g * H_ + h], l[h], a);
            m[g] = a;
        }
#pragma unroll
        for (int g = 0; g < H_; ++g) rowbuf[g * S_ + k] = m[g];
    }
    __syncthreads();

    const int warp = tid >> 5, lane = tid & 31;
    for (int row = warp; row < H_; row += 8) {
        float* r = rowbuf + row * S_;
        float mx = -1e30f;
        for (int k = lane; k < S_; k += 32) mx = fmaxf(mx, r[k]);
#pragma unroll
        for (int o = 16; o; o >>= 1) mx = fmaxf(mx, __shfl_xor_sync(0xffffffffu, mx, o));
        float s = 0.f;
        for (int k = lane; k < S_; k += 32) {
            const float e = fast_exp(r[k] - mx);
            r[k] = e;
            s += e;
        }
#pragma unroll
        for (int o = 16; o; o >>= 1) s += __shfl_xor_sync(0xffffffffu, s, o);
        const float inv = 1.0f / s;
        for (int k = lane; k < S_; k += 32) r[k] *= inv;
    }
    __syncthreads();

    for (int k = tid; k < S_; k += 256) {
        float pr[H_];
#pragma unroll
        for (int h = 0; h < H_; ++h) pr[h] = rowbuf[h * S_ + k];
#pragma unroll
        for (int g = 0; g < H_; ++g) {
            float a = wbw[g];
#pragma unroll
            for (int h = 0; h < H_; ++h) a = fmaf(wWw[g * H_ + h], pr[h], a);
            g_attn[base + (size_t)g * S_ * S_ + k] = a;
        }
    }
}

// ---------------------------------------------------------------------------
// K4: O = P V per (b,h). 48 batches of 1024x64x1024 (NN; V transposed on load)
// ---------------------------------------------------------------------------
__global__ void __launch_bounds__(256) k_av()
{
    __shared__ __align__(16) uint32_t Ah[2 * 128 * PW], Al[2 * 128 * PW];
    __shared__ __align__(16) uint32_t Bh[2 * 64 * PW], Bl[2 * 64 * PW];
    float acc[1][8][4] = {};
    const int bh = blockIdx.z;
    const float* P = g_attn + (size_t)bh * S_ * S_;
    const float* V = g_v + (size_t)bh * S_ * E_;
    const int m0 = blockIdx.y * 128;
    gemm_b3<CFGB, true>(P, S_, V, E_, S_, m0, 0, Ah, Al, Bh, Bl, acc);

    const int b = bh / H_, h = bh % H_;
    const int tid = threadIdx.x;
    const int warp = tid >> 5, lane = tid & 31;
    const int wm0 = (warp % 8) * 16;
    const int g = lane >> 2, tg = lane & 3;
#pragma unroll
    for (int nt = 0; nt < 8; ++nt) {
        const int n = nt * 8 + 2 * tg;
#pragma unroll
        for (int half = 0; half < 2; ++half) {
            const int q = m0 + wm0 + g + half * 8;
            *(float2*)(g_ctx + ((size_t)(b * S_ + q)) * D_ + h * E_ + n) =
                make_float2(acc[0][nt][half * 2], acc[0][nt][half * 2 + 1]);
        }
    }
}

// ---------------------------------------------------------------------------
// K5: out = ctx Wp^T + bp. 4096x768x768 (NT).
// ---------------------------------------------------------------------------
__global__ void __launch_bounds__(256) k_proj(const float* __restrict__ Wp,
                                              const float* __restrict__ bp,
                                              float* __restrict__ out)
{
    __shared__ __align__(16) uint32_t Ah[2 * 128 * PW], Al[2 * 128 * PW];
    __shared__ __align__(16) uint32_t Bh[2 * 128 * PW], Bl[2 * 128 * PW];
    float acc[2][8][4] = {};
    const int m0 = blockIdx.y * 128;
    const int n0 = blockIdx.x * 128;
    gemm_b3<CFGA, false>(g_ctx, D_, Wp, D_, D_, m0, n0, Ah, Al, Bh, Bl, acc);

    const int tid = threadIdx.x;
    const int warp = tid >> 5, lane = tid & 31;
    const int wm0 = (warp % 4) * 32, wn0 = (warp / 4) * 64;
    const int g = lane >> 2, tg = lane & 3;
#pragma unroll
    for (int mt = 0; mt < 2; ++mt)
#pragma unroll
        for (int nt = 0; nt < 8; ++nt) {
            const int n = n0 + wn0 + nt * 8 + 2 * tg;
            const float2 bias = make_float2(bp[n], bp[n + 1]);
#pragma unroll
            for (int half = 0; half < 2; ++half) {
                const int m = m0 + wm0 + mt * 16 + g + half * 8;
                *(float2*)(out + (size_t)m * D_ + n) =
                    make_float2(acc[mt][nt][half * 2] + bias.x,
                                acc[mt][nt][half * 2 + 1] + bias.y);
            }
        }
}

// ---------------------------------------------------------------------------
// Launch
// ---------------------------------------------------------------------------
extern "C" void kernel_launch(void* const* d_in, const int* in_sizes, int n_in,
                              void* d_out, int out_size)
{
    const float* x    = (const float*)d_in[0];
    const float* Wqkv = (const float*)d_in[1];
    const float* Wl   = (const float*)d_in[2];
    const float* bl   = (const float*)d_in[3];
    const float* Ww   = (const float*)d_in[4];
    const float* bw   = (const float*)d_in[5];
    const float* Wp   = (const float*)d_in[6];
    const float* bp   = (const float*)d_in[7];
    float* out = (float*)d_out;

    const int mix_smem = (H_ * S_ + 320) * (int)sizeof(float);
    cudaFuncSetAttribute(k_mix_softmax, cudaFuncAttributeMaxDynamicSharedMemorySize,
                         mix_smem);

    k_qkv<<<dim3(3 * D_ / 128, (B_ * S_) / 128), 256>>>(x, Wqkv);
    k_qk<<<dim3(S_ / 128, S_ / 128, B_ * H_), 256>>>();
    k_mix_softmax<<<B_ * S_, 256, mix_smem>>>(Wl, bl, Ww, bw);
    k_av<<<dim3(1, S_ / 128, B_ * H_), 256>>>();
    k_proj<<<dim3(D_ / 128, (B_ * S_) / 128), 256>>>(Wp, bp, out);
}

// round 12
// speedup vs baseline: 2.1064x; 1.1613x over previous
#include <cuda_runtime.h>
#include <cuda_bf16.h>
#include <cstdint>

#define B_ 4
#define S_ 1024
#define D_ 768
#define H_ 12
#define E_ 64

// ---------------------------------------------------------------------------
// Persistent device scratch
// ---------------------------------------------------------------------------
__device__ __align__(16) __nv_bfloat16 g_xh[B_ * S_ * D_];
__device__ __align__(16) __nv_bfloat16 g_xl[B_ * S_ * D_];
__device__ __align__(16) __nv_bfloat16 g_wqh[3 * D_ * D_];
__device__ __align__(16) __nv_bfloat16 g_wql[3 * D_ * D_];
__device__ __align__(16) __nv_bfloat16 g_wph_[D_ * D_];
__device__ __align__(16) __nv_bfloat16 g_wpl_[D_ * D_];
__device__ __align__(16) __nv_bfloat16 g_qh[B_ * H_ * S_ * E_];
__device__ __align__(16) __nv_bfloat16 g_ql[B_ * H_ * S_ * E_];
__device__ __align__(16) __nv_bfloat16 g_kh[B_ * H_ * S_ * E_];
__device__ __align__(16) __nv_bfloat16 g_kl[B_ * H_ * S_ * E_];
__device__ __align__(16) float         g_v [B_ * H_ * S_ * E_];
__device__ __align__(16) __nv_bfloat16 g_vth[B_ * H_ * E_ * S_]; // [b,h,e,s]
__device__ __align__(16) __nv_bfloat16 g_vtl[B_ * H_ * E_ * S_];
__device__ __align__(16) float         g_attn[(size_t)B_ * H_ * S_ * S_];
__device__ __align__(16) __nv_bfloat16 g_ah[(size_t)B_ * H_ * S_ * S_];
__device__ __align__(16) __nv_bfloat16 g_al[(size_t)B_ * H_ * S_ * S_];
__device__ __align__(16) __nv_bfloat16 g_ctxh[B_ * S_ * D_];
__device__ __align__(16) __nv_bfloat16 g_ctxl[B_ * S_ * D_];

// ---------------------------------------------------------------------------
// Helpers
// ---------------------------------------------------------------------------
__device__ __forceinline__ void bsplit(float a, float b, uint32_t& hi, uint32_t& lo)
{
    __nv_bfloat162 h = __floats2bfloat162_rn(a, b);
    const float ha = __bfloat162float(h.x), hb = __bfloat162float(h.y);
    __nv_bfloat162 l = __floats2bfloat162_rn(a - ha, b - hb);
    hi = *reinterpret_cast<uint32_t*>(&h);
    lo = *reinterpret_cast<uint32_t*>(&l);
}

__device__ __forceinline__ void mma_bf16(float c[4], const uint32_t a[4],
                                         const uint32_t* b)
{
    asm volatile(
        "mma.sync.aligned.m16n8k16.row.col.f32.bf16.bf16.f32 "
        "{%0,%1,%2,%3}, {%4,%5,%6,%7}, {%8,%9}, {%0,%1,%2,%3};\n"
        : "+f"(c[0]), "+f"(c[1]), "+f"(c[2]), "+f"(c[3])
        : "r"(a[0]), "r"(a[1]), "r"(a[2]), "r"(a[3]), "r"(b[0]), "r"(b[1]));
}

__device__ __forceinline__ void ldsm4(uint32_t r[4], uint32_t addr)
{
    asm volatile("ldmatrix.sync.aligned.m8n8.x4.shared.b16 {%0,%1,%2,%3}, [%4];"
                 : "=r"(r[0]), "=r"(r[1]), "=r"(r[2]), "=r"(r[3]) : "r"(addr));
}

__device__ __forceinline__ void cpa16(uint32_t dst, const void* src)
{
    asm volatile("cp.async.cg.shared.global [%0], [%1], 16;" :: "r"(dst), "l"(src));
}
__device__ __forceinline__ void cp_commit()
{
    asm volatile("cp.async.commit_group;" ::: "memory");
}
template<int N> __device__ __forceinline__ void cp_wait()
{
    asm volatile("cp.async.wait_group %0;" :: "n"(N) : "memory");
}

// ---------------------------------------------------------------------------
// bf16x3 GEMM core: pre-split bf16 inputs, cp.async 2-stage, ldmatrix frags.
//   acc[MT][NTT][4] (fp32) += A[m0.., K] * B[n0.., K]^T, K in chunks of 32.
// smem tile row pitch = 80 bytes (40 bf16): 8-row LDSM phases are
// conflict-free ((r*20) mod 32 covers all banks in groups of 4).
// ---------------------------------------------------------------------------
#define PITCHB 80

template<int BM, int BN, int WARPS_M, int MT, int NTT>
__device__ __forceinline__ void gemm_core(
    const __nv_bfloat16* __restrict__ Ahg, const __nv_bfloat16* __restrict__ Alg,
    int lda,
    const __nv_bfloat16* __restrict__ Bhg, const __nv_bfloat16* __restrict__ Blg,
    int ldb,
    int m0, int n0, int NC, char* sm, float acc[MT][NTT][4])
{
    constexpr int A_T = BM * PITCHB;
    constexpr int B_T = BN * PITCHB;
    constexpr int STAGE = 2 * A_T + 2 * B_T;

    const int tid = threadIdx.x;
    const int warp = tid >> 5, lane = tid & 31;
    const int wm0 = (warp % WARPS_M) * (MT * 16);
    const int wn0 = (warp / WARPS_M) * (NTT * 8);
    const uint32_t sbase = (uint32_t)__cvta_generic_to_shared(sm);

    Ahg += (size_t)m0 * lda;  Alg += (size_t)m0 * lda;
    Bhg += (size_t)n0 * ldb;  Blg += (size_t)n0 * ldb;

    auto load_tile = [&](uint32_t doff, const __nv_bfloat16* src, int ld,
                         int rows, int kc) {
        for (int i = tid; i < rows * 4; i += 256) {
            const int r = i >> 2, cc = i & 3;
            cpa16(sbase + doff + r * PITCHB + cc * 16,
                  src + (size_t)r * ld + kc * 32 + cc * 8);
        }
    };
    auto load_stage = [&](int st, int kc) {
        const uint32_t o = st * STAGE;
        load_tile(o,               Ahg, lda, BM, kc);
        load_tile(o + A_T,         Alg, lda, BM, kc);
        load_tile(o + 2 * A_T,     Bhg, ldb, BN, kc);
        load_tile(o + 2 * A_T + B_T, Blg, ldb, BN, kc);
        cp_commit();
    };

    // lane-dependent LDSM address components
    const int a_row = (lane & 7) + ((lane >> 3) & 1) * 8;     // + wm0 + mt*16
    const int a_col = ((lane >> 4) & 1) * 16;                 // + ks*32
    const int b_row = (lane & 7) + ((lane >> 4) & 1) * 8;     // + wn0 + nt2*16
    const int b_col = ((lane >> 3) & 1) * 16;                 // + ks*32

    auto compute = [&](int st) {
        const uint32_t o = sbase + st * STAGE;
#pragma unroll
        for (int ks = 0; ks < 2; ++ks) {
            uint32_t ah[MT][4], al[MT][4];
#pragma unroll
            for (int mt = 0; mt < MT; ++mt) {
                const uint32_t ra =
                    o + (wm0 + mt * 16 + a_row) * PITCHB + ks * 32 + a_col;
                ldsm4(ah[mt], ra);
                ldsm4(al[mt], ra + A_T);
            }
#pragma unroll
            for (int nt2 = 0; nt2 < NTT / 2; ++nt2) {
                uint32_t bh[4], bl[4];
                const uint32_t rb = o + 2 * A_T +
                    (wn0 + nt2 * 16 + b_row) * PITCHB + ks * 32 + b_col;
                ldsm4(bh, rb);
                ldsm4(bl, rb + B_T);
#pragma unroll
                for (int mt = 0; mt < MT; ++mt) {
                    mma_bf16(acc[mt][2 * nt2],     ah[mt], bh);
                    mma_bf16(acc[mt][2 * nt2],     ah[mt], bl);
                    mma_bf16(acc[mt][2 * nt2],     al[mt], bh);
                    mma_bf16(acc[mt][2 * nt2 + 1], ah[mt], bh + 2);
                    mma_bf16(acc[mt][2 * nt2 + 1], ah[mt], bl + 2);
                    mma_bf16(acc[mt][2 * nt2 + 1], al[mt], bh + 2);
                }
            }
        }
    };

    load_stage(0, 0);
    for (int c = 0; c < NC; ++c) {
        if (c + 1 < NC) {
            load_stage((c + 1) & 1, c + 1);
            cp_wait<1>();
        } else {
            cp_wait<0>();
        }
        __syncthreads();
        compute(c & 1);
        __syncthreads();
    }
}

// ---------------------------------------------------------------------------
// Pre-pass: fp32 -> bf16 hi/lo split
// ---------------------------------------------------------------------------
__global__ void k_split(const float* __restrict__ src, __nv_bfloat16* __restrict__ h,
                        __nv_bfloat16* __restrict__ l, int npairs)
{
    const int i = blockIdx.x * blockDim.x + threadIdx.x;
    if (i < npairs) {
        const float2 v = ((const float2*)src)[i];
        uint32_t hw, lw;
        bsplit(v.x, v.y, hw, lw);
        ((uint32_t*)h)[i] = hw;
        ((uint32_t*)l)[i] = lw;
    }
}

// V [b,h,s,e] fp32 -> transposed split [b,h,e,s] bf16 hi/lo
__global__ void __launch_bounds__(256) k_vtrans()
{
    __shared__ float t[64][65];
    const int s0 = blockIdx.x * 64;
    const int bh = blockIdx.y;
    const int tid = threadIdx.x;
    for (int idx = tid; idx < 4096; idx += 256) {
        const int e = idx & 63, r = idx >> 6;
        t[e][r] = g_v[((size_t)bh * 1024 + s0 + r) * 64 + e];
    }
    __syncthreads();
    for (int idx = tid; idx < 2048; idx += 256) {
        const int e = idx >> 5, sp = idx & 31;
        uint32_t hw, lw;
        bsplit(t[e][2 * sp], t[e][2 * sp + 1], hw, lw);
        const size_t w = ((size_t)(bh * 64 + e) * 1024 + s0) / 2 + sp;
        ((uint32_t*)g_vth)[w] = hw;
        ((uint32_t*)g_vtl)[w] = lw;
    }
}

// ---------------------------------------------------------------------------
// K1: QKV. [4096,2304] = x * Wqkv^T; scatter q/k split bf16, v fp32.
// ---------------------------------------------------------------------------
__global__ void __launch_bounds__(256) k_qkv()
{
    extern __shared__ char sm[];
    float acc[2][8][4] = {};
    const int m0 = blockIdx.y * 128;
    const int n0 = blockIdx.x * 128;
    gemm_core<128, 128, 4, 2, 8>(g_xh, g_xl, D_, g_wqh, g_wql, D_,
                                 m0, n0, D_ / 32, sm, acc);

    const int tid = threadIdx.x;
    const int warp = tid >> 5, lane = tid & 31;
    const int wm0 = (warp % 4) * 32, wn0 = (warp / 4) * 64;
    const int g = lane >> 2, tg = lane & 3;
    const int t = n0 / D_;
    const int rem0 = n0 % D_;
    __nv_bfloat16* ph = (t == 0) ? g_qh : g_kh;
    __nv_bfloat16* pl = (t == 0) ? g_ql : g_kl;
#pragma unroll
    for (int mt = 0; mt < 2; ++mt)
#pragma unroll
        for (int nt = 0; nt < 8; ++nt) {
            const int rem = rem0 + wn0 + nt * 8 + 2 * tg;
            const int h = rem >> 6, e = rem & 63;
#pragma unroll
            for (int half = 0; half < 2; ++half) {
                const int m = m0 + wm0 + mt * 16 + g + half * 8;
                const int b = m >> 10, s = m & 1023;
                const size_t off = (((size_t)(b * H_ + h)) * S_ + s) * E_ + e;
                const float f0 = acc[mt][nt][half * 2];
                const float f1 = acc[mt][nt][half * 2 + 1];
                if (t == 2) {
                    *(float2*)(g_v + off) = make_float2(f0, f1);
                } else {
                    uint32_t hw, lw;
                    bsplit(f0, f1, hw, lw);
                    ((uint32_t*)ph)[off >> 1] = hw;
                    ((uint32_t*)pl)[off >> 1] = lw;
                }
            }
        }
}

// ---------------------------------------------------------------------------
// K2: logits = Q K^T per (b,h). K=64.
// ---------------------------------------------------------------------------
__global__ void __launch_bounds__(256) k_qk()
{
    extern __shared__ char sm[];
    float acc[2][8][4] = {};
    const int bh = blockIdx.z;
    const int m0 = blockIdx.y * 128;
    const int n0 = blockIdx.x * 128;
    gemm_core<128, 128, 4, 2, 8>(
        g_qh + (size_t)bh * S_ * E_, g_ql + (size_t)bh * S_ * E_, E_,
        g_kh + (size_t)bh * S_ * E_, g_kl + (size_t)bh * S_ * E_, E_,
        m0, n0, E_ / 32, sm, acc);

    float* C = g_attn + (size_t)bh * S_ * S_;
    const int tid = threadIdx.x;
    const int warp = tid >> 5, lane = tid & 31;
    const int wm0 = (warp % 4) * 32, wn0 = (warp / 4) * 64;
    const int g = lane >> 2, tg = lane & 3;
#pragma unroll
    for (int mt = 0; mt < 2; ++mt)
#pragma unroll
        for (int nt = 0; nt < 8; ++nt) {
            const int n = n0 + wn0 + nt * 8 + 2 * tg;
#pragma unroll
            for (int half = 0; half < 2; ++half) {
                const int m = m0 + wm0 + mt * 16 + g + half * 8;
                *(float2*)(C + (size_t)m * S_ + n) =
                    make_float2(acc[mt][nt][half * 2], acc[mt][nt][half * 2 + 1]);
            }
        }
}

// ---------------------------------------------------------------------------
// K3: mix1 -> softmax -> mix2; writes probs split bf16 hi/lo.
// ---------------------------------------------------------------------------
__device__ __forceinline__ float fast_exp(float x)
{
    const float y = x * 1.4426950408889634f;
    const float r = rintf(y);
    const float f = y - r;
    float p = 1.5403530e-4f;
    p = fmaf(p, f, 1.3333558e-3f);
    p = fmaf(p, f, 9.6181291e-3f);
    p = fmaf(p, f, 5.5504109e-2f);
    p = fmaf(p, f, 2.4022651e-1f);
    p = fmaf(p, f, 6.9314718e-1f);
    p = fmaf(p, f, 1.0f);
    const int ri = (int)fmaxf(r, -126.0f);
    return __int_as_float(__float_as_int(p) + (ri << 23));
}

__global__ void __launch_bounds__(256) k_mix_softmax(const float* __restrict__ Wl,
                                                     const float* __restrict__ bl,
                                                     const float* __restrict__ Ww,
                                                     const float* __restrict__ bw)
{
    extern __shared__ __align__(16) float smf[];
    float* rowbuf = smf;
    float* wWl = smf + H_ * S_;
    float* wbl = wWl + 144;
    float* wWw = wbl + 12;
    float* wbw = wWw + 144;

    const int tid = threadIdx.x;
    const int bq = blockIdx.x;
    const int b = bq >> 10, q = bq & 1023;

    for (int i = tid; i < 144; i += 256) { wWl[i] = Wl[i]; wWw[i] = Ww[i]; }
    if (tid < 12) { wbl[tid] = bl[tid]; wbw[tid] = bw[tid]; }

    const size_t base = ((size_t)b * H_) * S_ * S_ + (size_t)q * S_;
    for (int h = 0; h < H_; ++h) {
        const float4* src = (const float4*)(g_attn + base + (size_t)h * S_ * S_);
        ((float4*)(rowbuf + h * S_))[tid] = src[tid];
    }
    __syncthreads();

    for (int k = tid; k < S_; k += 256) {
        float l[H_];
#pragma unroll
        for (int h = 0; h < H_; ++h) l[h] = rowbuf[h * S_ + k];
        float m[H_];
#pragma unroll
        for (int g = 0; g < H_; ++g) {
            float a = wbl[g];
#pragma unroll
            for (int h = 0; h < H_; ++h) a = fmaf(wWl[g * H_ + h], l[h], a);
            m[g] = a;
        }
#pragma unroll
        for (int g = 0; g < H_; ++g) rowbuf[g * S_ + k] = m[g];
    }
    __syncthreads();

    const int warp = tid >> 5, lane = tid & 31;
    for (int row = warp; row < H_; row += 8) {
        float* r = rowbuf + row * S_;
        float mx = -1e30f;
        for (int k = lane; k < S_; k += 32) mx = fmaxf(mx, r[k]);
#pragma unroll
        for (int o = 16; o; o >>= 1) mx = fmaxf(mx, __shfl_xor_sync(0xffffffffu, mx, o));
        float s = 0.f;
        for (int k = lane; k < S_; k += 32) {
            const float e = fast_exp(r[k] - mx);
            r[k] = e;
            s += e;
        }
#pragma unroll
        for (int o = 16; o; o >>= 1) s += __shfl_xor_sync(0xffffffffu, s, o);
        const float inv = 1.0f / s;
        for (int k = lane; k < S_; k += 32) r[k] *= inv;
    }
    __syncthreads();

    for (int k = tid; k < S_; k += 256) {
        float pr[H_];
#pragma unroll
        for (int h = 0; h < H_; ++h) pr[h] = rowbuf[h * S_ + k];
#pragma unroll
        for (int g = 0; g < H_; ++g) {
            float a = wbw[g];
#pragma unroll
            for (int h = 0; h < H_; ++h) a = fmaf(wWw[g * H_ + h], pr[h], a);
            rowbuf[g * S_ + k] = a;
        }
    }
    __syncthreads();

    const size_t base2 = base / 2;
    for (int idx = tid; idx < H_ * (S_ / 2); idx += 256) {
        const int g = idx >> 9, kp = idx & 511;
        uint32_t hw, lw;
        bsplit(rowbuf[g * S_ + 2 * kp], rowbuf[g * S_ + 2 * kp + 1], hw, lw);
        const size_t w = base2 + (size_t)g * (S_ * S_ / 2) + kp;
        ((uint32_t*)g_ah)[w] = hw;
        ((uint32_t*)g_al)[w] = lw;
    }
}

// ---------------------------------------------------------------------------
// K4: O = P V per (b,h). A = probs split [S,S], B = V^T split [E,S]. K=1024.
// ---------------------------------------------------------------------------
__global__ void __launch_bounds__(256) k_av()
{
    extern __shared__ char sm[];
    float acc[1][8][4] = {};
    const int bh = blockIdx.z;
    const int m0 = blockIdx.y * 128;
    gemm_core<128, 64, 8, 1, 8>(
        g_ah + (size_t)bh * S_ * S_, g_al + (size_t)bh * S_ * S_, S_,
        g_vth + (size_t)bh * E_ * S_, g_vtl + (size_t)bh * E_ * S_, S_,
        m0, 0, S_ / 32, sm, acc);

    const int b = bh / H_, h = bh % H_;
    const int tid = threadIdx.x;
    const int warp = tid >> 5, lane = tid & 31;
    const int wm0 = (warp % 8) * 16;
    const int g = lane >> 2, tg = lane & 3;
#pragma unroll
    for (int nt = 0; nt < 8; ++nt) {
        const int n = nt * 8 + 2 * tg;
#pragma unroll
        for (int half = 0; half < 2; ++half) {
            const int q = m0 + wm0 + g + half * 8;
            uint32_t hw, lw;
            bsplit(acc[0][nt][half * 2], acc[0][nt][half * 2 + 1], hw, lw);
            const size_t off = ((size_t)(b * S_ + q)) * D_ + h * E_ + n;
            ((uint32_t*)g_ctxh)[off >> 1] = hw;
            ((uint32_t*)g_ctxl)[off >> 1] = lw;
        }
    }
}

// ---------------------------------------------------------------------------
// K5: out = ctx Wp^T + bp.
// ---------------------------------------------------------------------------
__global__ void __launch_bounds__(256) k_proj(const float* __restrict__ bp,
                                              float* __restrict__ out)
{
    extern __shared__ char sm[];
    float acc[2][8][4] = {};
    const int m0 = blockIdx.y * 128;
    const int n0 = blockIdx.x * 128;
    gemm_core<128, 128, 4, 2, 8>(g_ctxh, g_ctxl, D_, g_wph_, g_wpl_, D_,
                                 m0, n0, D_ / 32, sm, acc);

    const int tid = threadIdx.x;
    const int warp = tid >> 5, lane = tid & 31;
    const int wm0 = (warp % 4) * 32, wn0 = (warp / 4) * 64;
    const int g = lane >> 2, tg = lane & 3;
#pragma unroll
    for (int mt = 0; mt < 2; ++mt)
#pragma unroll
        for (int nt = 0; nt < 8; ++nt) {
            const int n = n0 + wn0 + nt * 8 + 2 * tg;
            const float2 bias = make_float2(bp[n], bp[n + 1]);
#pragma unroll
            for (int half = 0; half < 2; ++half) {
                const int m = m0 + wm0 + mt * 16 + g + half * 8;
                *(float2*)(out + (size_t)m * D_ + n) =
                    make_float2(acc[mt][nt][half * 2] + bias.x,
                                acc[mt][nt][half * 2 + 1] + bias.y);
            }
        }
}

// ---------------------------------------------------------------------------
// Launch
// ---------------------------------------------------------------------------
extern "C" void kernel_launch(void* const* d_in, const int* in_sizes, int n_in,
                              void* d_out, int out_size)
{
    const float* x    = (const float*)d_in[0];
    const float* Wqkv = (const float*)d_in[1];
    const float* Wl   = (const float*)d_in[2];
    const float* bl   = (const float*)d_in[3];
    const float* Ww   = (const float*)d_in[4];
    const float* bw   = (const float*)d_in[5];
    const float* Wp   = (const float*)d_in[6];
    const float* bp   = (const float*)d_in[7];
    float* out = (float*)d_out;

    // smem: 2 stages * (2*A + 2*B) tiles at 80B pitch
    const int SM_A = 2 * (2 * 128 * PITCHB + 2 * 128 * PITCHB);  // 81920
    const int SM_B = 2 * (2 * 128 * PITCHB + 2 * 64 * PITCHB);   // 61440
    const int mix_smem = (H_ * S_ + 320) * (int)sizeof(float);

    cudaFuncSetAttribute(k_qkv,  cudaFuncAttributeMaxDynamicSharedMemorySize, SM_A);
    cudaFuncSetAttribute(k_qk,   cudaFuncAttributeMaxDynamicSharedMemorySize, SM_A);
    cudaFuncSetAttribute(k_av,   cudaFuncAttributeMaxDynamicSharedMemorySize, SM_B);
    cudaFuncSetAttribute(k_proj, cudaFuncAttributeMaxDynamicSharedMemorySize, SM_A);
    cudaFuncSetAttribute(k_mix_softmax, cudaFuncAttributeMaxDynamicSharedMemorySize,
                         mix_smem);

    __nv_bfloat16 *xh, *xl, *wqh, *wql, *wph, *wpl;
    cudaGetSymbolAddress((void**)&xh,  g_xh);
    cudaGetSymbolAddress((void**)&xl,  g_xl);
    cudaGetSymbolAddress((void**)&wqh, g_wqh);
    cudaGetSymbolAddress((void**)&wql, g_wql);
    cudaGetSymbolAddress((void**)&wph, g_wph_);
    cudaGetSymbolAddress((void**)&wpl, g_wpl_);

    const int nx = B_ * S_ * D_ / 2;
    const int nq = 3 * D_ * D_ / 2;
    const int np = D_ * D_ / 2;
    k_split<<<(nx + 255) / 256, 256>>>(x, xh, xl, nx);
    k_split<<<(nq + 255) / 256, 256>>>(Wqkv, wqh, wql, nq);
    k_split<<<(np + 255) / 256, 256>>>(Wp, wph, wpl, np);

    k_qkv<<<dim3(3 * D_ / 128, (B_ * S_) / 128), 256, SM_A>>>();
    k_vtrans<<<dim3(S_ / 64, B_ * H_), 256>>>();
    k_qk<<<dim3(S_ / 128, S_ / 128, B_ * H_), 256, SM_A>>>();
    k_mix_softmax<<<B_ * S_, 256, mix_smem>>>(Wl, bl, Ww, bw);
    k_av<<<dim3(1, S_ / 128, B_ * H_), 256, SM_B>>>();
    k_proj<<<dim3(D_ / 128, (B_ * S_) / 128), 256, SM_A>>>(bp, out);
}

// round 13
// speedup vs baseline: 2.1533x; 1.0222x over previous
#include <cuda_runtime.h>
#include <cuda_bf16.h>
#include <cstdint>

#define B_ 4
#define S_ 1024
#define D_ 768
#define H_ 12
#define E_ 64

// ---------------------------------------------------------------------------
// Persistent device scratch
// ---------------------------------------------------------------------------
__device__ __align__(16) __nv_bfloat16 g_xh[B_ * S_ * D_];
__device__ __align__(16) __nv_bfloat16 g_xl[B_ * S_ * D_];
__device__ __align__(16) __nv_bfloat16 g_wqh[3 * D_ * D_];
__device__ __align__(16) __nv_bfloat16 g_wql[3 * D_ * D_];
__device__ __align__(16) __nv_bfloat16 g_wph_[D_ * D_];
__device__ __align__(16) __nv_bfloat16 g_wpl_[D_ * D_];
__device__ __align__(16) __nv_bfloat16 g_qh[B_ * H_ * S_ * E_];
__device__ __align__(16) __nv_bfloat16 g_ql[B_ * H_ * S_ * E_];
__device__ __align__(16) __nv_bfloat16 g_kh[B_ * H_ * S_ * E_];
__device__ __align__(16) __nv_bfloat16 g_kl[B_ * H_ * S_ * E_];
__device__ __align__(16) float         g_v [B_ * H_ * S_ * E_];
__device__ __align__(16) __nv_bfloat16 g_vth[B_ * H_ * E_ * S_]; // [b,h,e,s]
__device__ __align__(16) __nv_bfloat16 g_vtl[B_ * H_ * E_ * S_];
__device__ __align__(16) float         g_attn[(size_t)B_ * H_ * S_ * S_];
__device__ __align__(16) __nv_bfloat16 g_ah[(size_t)B_ * H_ * S_ * S_];
__device__ __align__(16) __nv_bfloat16 g_al[(size_t)B_ * H_ * S_ * S_];
__device__ __align__(16) __nv_bfloat16 g_ctxh[B_ * S_ * D_];
__device__ __align__(16) __nv_bfloat16 g_ctxl[B_ * S_ * D_];

// ---------------------------------------------------------------------------
// Helpers
// ---------------------------------------------------------------------------
__device__ __forceinline__ void bsplit(float a, float b, uint32_t& hi, uint32_t& lo)
{
    __nv_bfloat162 h = __floats2bfloat162_rn(a, b);
    const float ha = __bfloat162float(h.x), hb = __bfloat162float(h.y);
    __nv_bfloat162 l = __floats2bfloat162_rn(a - ha, b - hb);
    hi = *reinterpret_cast<uint32_t*>(&h);
    lo = *reinterpret_cast<uint32_t*>(&l);
}

__device__ __forceinline__ void mma_bf16(float c[4], const uint32_t a[4],
                                         const uint32_t* b)
{
    asm volatile(
        "mma.sync.aligned.m16n8k16.row.col.f32.bf16.bf16.f32 "
        "{%0,%1,%2,%3}, {%4,%5,%6,%7}, {%8,%9}, {%0,%1,%2,%3};\n"
        : "+f"(c[0]), "+f"(c[1]), "+f"(c[2]), "+f"(c[3])
        : "r"(a[0]), "r"(a[1]), "r"(a[2]), "r"(a[3]), "r"(b[0]), "r"(b[1]));
}

__device__ __forceinline__ void ldsm4(uint32_t r[4], uint32_t addr)
{
    asm volatile("ldmatrix.sync.aligned.m8n8.x4.shared.b16 {%0,%1,%2,%3}, [%4];"
                 : "=r"(r[0]), "=r"(r[1]), "=r"(r[2]), "=r"(r[3]) : "r"(addr));
}

__device__ __forceinline__ void cpa16(uint32_t dst, const void* src)
{
    asm volatile("cp.async.cg.shared.global [%0], [%1], 16;" :: "r"(dst), "l"(src));
}
__device__ __forceinline__ void cp_commit()
{
    asm volatile("cp.async.commit_group;" ::: "memory");
}
template<int N> __device__ __forceinline__ void cp_wait()
{
    asm volatile("cp.async.wait_group %0;" :: "n"(N) : "memory");
}

// ---------------------------------------------------------------------------
// bf16x3 GEMM core. Changes vs R12:
//  - term-major MMA ordering over groups of NTG n-tiles: same-accumulator
//    reuse spaced MT*NTG*2 MMAs apart (kills the hh->hl->lh RAW chain)
//  - single __syncthreads per K-chunk (wait -> sync -> next loads -> compute)
// ---------------------------------------------------------------------------
#define PITCHB 80

template<int BM, int BN, int WARPS_M, int MT, int NTT, int NTG>
__device__ __forceinline__ void gemm_core(
    const __nv_bfloat16* __restrict__ Ahg, const __nv_bfloat16* __restrict__ Alg,
    int lda,
    const __nv_bfloat16* __restrict__ Bhg, const __nv_bfloat16* __restrict__ Blg,
    int ldb,
    int m0, int n0, int NC, char* sm, float acc[MT][NTT][4])
{
    constexpr int A_T = BM * PITCHB;
    constexpr int B_T = BN * PITCHB;
    constexpr int STAGE = 2 * A_T + 2 * B_T;

    const int tid = threadIdx.x;
    const int warp = tid >> 5, lane = tid & 31;
    const int wm0 = (warp % WARPS_M) * (MT * 16);
    const int wn0 = (warp / WARPS_M) * (NTT * 8);
    const uint32_t sbase = (uint32_t)__cvta_generic_to_shared(sm);

    Ahg += (size_t)m0 * lda;  Alg += (size_t)m0 * lda;
    Bhg += (size_t)n0 * ldb;  Blg += (size_t)n0 * ldb;

    auto load_tile = [&](uint32_t doff, const __nv_bfloat16* src, int ld,
                         int rows, int kc) {
        for (int i = tid; i < rows * 4; i += 256) {
            const int r = i >> 2, cc = i & 3;
            cpa16(sbase + doff + r * PITCHB + cc * 16,
                  src + (size_t)r * ld + kc * 32 + cc * 8);
        }
    };
    auto load_stage = [&](int st, int kc) {
        const uint32_t o = st * STAGE;
        load_tile(o,               Ahg, lda, BM, kc);
        load_tile(o + A_T,         Alg, lda, BM, kc);
        load_tile(o + 2 * A_T,     Bhg, ldb, BN, kc);
        load_tile(o + 2 * A_T + B_T, Blg, ldb, BN, kc);
        cp_commit();
    };

    const int a_row = (lane & 7) + ((lane >> 3) & 1) * 8;
    const int a_col = ((lane >> 4) & 1) * 16;
    const int b_row = (lane & 7) + ((lane >> 4) & 1) * 8;
    const int b_col = ((lane >> 3) & 1) * 16;

    auto compute = [&](int st) {
        const uint32_t o = sbase + st * STAGE;
#pragma unroll
        for (int ks = 0; ks < 2; ++ks) {
            uint32_t ah[MT][4], al[MT][4];
#pragma unroll
            for (int mt = 0; mt < MT; ++mt) {
                const uint32_t ra =
                    o + (wm0 + mt * 16 + a_row) * PITCHB + ks * 32 + a_col;
                ldsm4(ah[mt], ra);
                ldsm4(al[mt], ra + A_T);
            }
#pragma unroll
            for (int g0 = 0; g0 < NTT / 2; g0 += NTG) {
                uint32_t bh[NTG][4], bl[NTG][4];
#pragma unroll
                for (int j = 0; j < NTG; ++j) {
                    const uint32_t rb = o + 2 * A_T +
                        (wn0 + (g0 + j) * 16 + b_row) * PITCHB + ks * 32 + b_col;
                    ldsm4(bh[j], rb);
                    ldsm4(bl[j], rb + B_T);
                }
                // term hh — MT*NTG*2 independent MMAs
#pragma unroll
                for (int mt = 0; mt < MT; ++mt)
#pragma unroll
                    for (int j = 0; j < NTG; ++j) {
                        mma_bf16(acc[mt][2 * (g0 + j)],     ah[mt], bh[j]);
                        mma_bf16(acc[mt][2 * (g0 + j) + 1], ah[mt], bh[j] + 2);
                    }
                // term hl
#pragma unroll
                for (int mt = 0; mt < MT; ++mt)
#pragma unroll
                    for (int j = 0; j < NTG; ++j) {
                        mma_bf16(acc[mt][2 * (g0 + j)],     ah[mt], bl[j]);
                        mma_bf16(acc[mt][2 * (g0 + j) + 1], ah[mt], bl[j] + 2);
                    }
                // term lh
#pragma unroll
                for (int mt = 0; mt < MT; ++mt)
#pragma unroll
                    for (int j = 0; j < NTG; ++j) {
                        mma_bf16(acc[mt][2 * (g0 + j)],     al[mt], bh[j]);
                        mma_bf16(acc[mt][2 * (g0 + j) + 1], al[mt], bh[j] + 2);
                    }
            }
        }
    };

    // single-sync 2-stage pipeline
    load_stage(0, 0);
    for (int c = 0; c < NC; ++c) {
        cp_wait<0>();
        __syncthreads();
        if (c + 1 < NC) load_stage((c + 1) & 1, c + 1);
        compute(c & 1);
    }
}

// ---------------------------------------------------------------------------
// Pre-pass: fp32 -> bf16 hi/lo split
// ---------------------------------------------------------------------------
__global__ void k_split(const float* __restrict__ src, __nv_bfloat16* __restrict__ h,
                        __nv_bfloat16* __restrict__ l, int npairs)
{
    const int i = blockIdx.x * blockDim.x + threadIdx.x;
    if (i < npairs) {
        const float2 v = ((const float2*)src)[i];
        uint32_t hw, lw;
        bsplit(v.x, v.y, hw, lw);
        ((uint32_t*)h)[i] = hw;
        ((uint32_t*)l)[i] = lw;
    }
}

// V [b,h,s,e] fp32 -> transposed split [b,h,e,s] bf16 hi/lo
__global__ void __launch_bounds__(256) k_vtrans()
{
    __shared__ float t[64][65];
    const int s0 = blockIdx.x * 64;
    const int bh = blockIdx.y;
    const int tid = threadIdx.x;
    for (int idx = tid; idx < 4096; idx += 256) {
        const int e = idx & 63, r = idx >> 6;
        t[e][r] = g_v[((size_t)bh * 1024 + s0 + r) * 64 + e];
    }
    __syncthreads();
    for (int idx = tid; idx < 2048; idx += 256) {
        const int e = idx >> 5, sp = idx & 31;
        uint32_t hw, lw;
        bsplit(t[e][2 * sp], t[e][2 * sp + 1], hw, lw);
        const size_t w = ((size_t)(bh * 64 + e) * 1024 + s0) / 2 + sp;
        ((uint32_t*)g_vth)[w] = hw;
        ((uint32_t*)g_vtl)[w] = lw;
    }
}

// ---------------------------------------------------------------------------
// K1: QKV. [4096,2304] = x * Wqkv^T; scatter q/k split bf16, v fp32.
// ---------------------------------------------------------------------------
__global__ void __launch_bounds__(256, 2) k_qkv()
{
    extern __shared__ char sm[];
    float acc[2][8][4] = {};
    const int m0 = blockIdx.y * 128;
    const int n0 = blockIdx.x * 128;
    gemm_core<128, 128, 4, 2, 8, 2>(g_xh, g_xl, D_, g_wqh, g_wql, D_,
                                    m0, n0, D_ / 32, sm, acc);

    const int tid = threadIdx.x;
    const int warp = tid >> 5, lane = tid & 31;
    const int wm0 = (warp % 4) * 32, wn0 = (warp / 4) * 64;
    const int g = lane >> 2, tg = lane & 3;
    const int t = n0 / D_;
    const int rem0 = n0 % D_;
    __nv_bfloat16* ph = (t == 0) ? g_qh : g_kh;
    __nv_bfloat16* pl = (t == 0) ? g_ql : g_kl;
#pragma unroll
    for (int mt = 0; mt < 2; ++mt)
#pragma unroll
        for (int nt = 0; nt < 8; ++nt) {
            const int rem = rem0 + wn0 + nt * 8 + 2 * tg;
            const int h = rem >> 6, e = rem & 63;
#pragma unroll
            for (int half = 0; half < 2; ++half) {
                const int m = m0 + wm0 + mt * 16 + g + half * 8;
                const int b = m >> 10, s = m & 1023;
                const size_t off = (((size_t)(b * H_ + h)) * S_ + s) * E_ + e;
                const float f0 = acc[mt][nt][half * 2];
                const float f1 = acc[mt][nt][half * 2 + 1];
                if (t == 2) {
                    *(float2*)(g_v + off) = make_float2(f0, f1);
                } else {
                    uint32_t hw, lw;
                    bsplit(f0, f1, hw, lw);
                    ((uint32_t*)ph)[off >> 1] = hw;
                    ((uint32_t*)pl)[off >> 1] = lw;
                }
            }
        }
}

// ---------------------------------------------------------------------------
// K2: logits = Q K^T per (b,h). K=64.
// ---------------------------------------------------------------------------
__global__ void __launch_bounds__(256, 2) k_qk()
{
    extern __shared__ char sm[];
    float acc[2][8][4] = {};
    const int bh = blockIdx.z;
    const int m0 = blockIdx.y * 128;
    const int n0 = blockIdx.x * 128;
    gemm_core<128, 128, 4, 2, 8, 2>(
        g_qh + (size_t)bh * S_ * E_, g_ql + (size_t)bh * S_ * E_, E_,
        g_kh + (size_t)bh * S_ * E_, g_kl + (size_t)bh * S_ * E_, E_,
        m0, n0, E_ / 32, sm, acc);

    float* C = g_attn + (size_t)bh * S_ * S_;
    const int tid = threadIdx.x;
    const int warp = tid >> 5, lane = tid & 31;
    const int wm0 = (warp % 4) * 32, wn0 = (warp / 4) * 64;
    const int g = lane >> 2, tg = lane & 3;
#pragma unroll
    for (int mt = 0; mt < 2; ++mt)
#pragma unroll
        for (int nt = 0; nt < 8; ++nt) {
            const int n = n0 + wn0 + nt * 8 + 2 * tg;
#pragma unroll
            for (int half = 0; half < 2; ++half) {
                const int m = m0 + wm0 + mt * 16 + g + half * 8;
                *(float2*)(C + (size_t)m * S_ + n) =
                    make_float2(acc[mt][nt][half * 2], acc[mt][nt][half * 2 + 1]);
            }
        }
}

// ---------------------------------------------------------------------------
// K3: mix1 -> softmax -> mix2; writes probs split bf16 hi/lo.
// ---------------------------------------------------------------------------
__device__ __forceinline__ float fast_exp(float x)
{
    const float y = x * 1.4426950408889634f;
    const float r = rintf(y);
    const float f = y - r;
    float p = 1.5403530e-4f;
    p = fmaf(p, f, 1.3333558e-3f);
    p = fmaf(p, f, 9.6181291e-3f);
    p = fmaf(p, f, 5.5504109e-2f);
    p = fmaf(p, f, 2.4022651e-1f);
    p = fmaf(p, f, 6.9314718e-1f);
    p = fmaf(p, f, 1.0f);
    const int ri = (int)fmaxf(r, -126.0f);
    return __int_as_float(__float_as_int(p) + (ri << 23));
}

__global__ void __launch_bounds__(256) k_mix_softmax(const float* __restrict__ Wl,
                                                     const float* __restrict__ bl,
                                                     const float* __restrict__ Ww,
                                                     const float* __restrict__ bw)
{
    extern __shared__ __align__(16) float smf[];
    float* rowbuf = smf;
    float* wWl = smf + H_ * S_;
    float* wbl = wWl + 144;
    float* wWw = wbl + 12;
    float* wbw = wWw + 144;

    const int tid = threadIdx.x;
    const int bq = blockIdx.x;
    const int b = bq >> 10, q = bq & 1023;

    for (int i = tid; i < 144; i += 256) { wWl[i] = Wl[i]; wWw[i] = Ww[i]; }
    if (tid < 12) { wbl[tid] = bl[tid]; wbw[tid] = bw[tid]; }

    const size_t base = ((size_t)b * H_) * S_ * S_ + (size_t)q * S_;
    for (int h = 0; h < H_; ++h) {
        const float4* src = (const float4*)(g_attn + base + (size_t)h * S_ * S_);
        ((float4*)(rowbuf + h * S_))[tid] = src[tid];
    }
    __syncthreads();

    for (int k = tid; k < S_; k += 256) {
        float l[H_];
#pragma unroll
        for (int h = 0; h < H_; ++h) l[h] = rowbuf[h * S_ + k];
        float m[H_];
#pragma unroll
        for (int g = 0; g < H_; ++g) {
            float a = wbl[g];
#pragma unroll
            for (int h = 0; h < H_; ++h) a = fmaf(wWl[g * H_ + h], l[h], a);
            m[g] = a;
        }
#pragma unroll
        for (int g = 0; g < H_; ++g) rowbuf[g * S_ + k] = m[g];
    }
    __syncthreads();

    const int warp = tid >> 5, lane = tid & 31;
    for (int row = warp; row < H_; row += 8) {
        float* r = rowbuf + row * S_;
        float mx = -1e30f;
        for (int k = lane; k < S_; k += 32) mx = fmaxf(mx, r[k]);
#pragma unroll
        for (int o = 16; o; o >>= 1) mx = fmaxf(mx, __shfl_xor_sync(0xffffffffu, mx, o));
        float s = 0.f;
        for (int k = lane; k < S_; k += 32) {
            const float e = fast_exp(r[k] - mx);
            r[k] = e;
            s += e;
        }
#pragma unroll
        for (int o = 16; o; o >>= 1) s += __shfl_xor_sync(0xffffffffu, s, o);
        const float inv = 1.0f / s;
        for (int k = lane; k < S_; k += 32) r[k] *= inv;
    }
    __syncthreads();

    for (int k = tid; k < S_; k += 256) {
        float pr[H_];
#pragma unroll
        for (int h = 0; h < H_; ++h) pr[h] = rowbuf[h * S_ + k];
#pragma unroll
        for (int g = 0; g < H_; ++g) {
            float a = wbw[g];
#pragma unroll
            for (int h = 0; h < H_; ++h) a = fmaf(wWw[g * H_ + h], pr[h], a);
            rowbuf[g * S_ + k] = a;
        }
    }
    __syncthreads();

    const size_t base2 = base / 2;
    for (int idx = tid; idx < H_ * (S_ / 2); idx += 256) {
        const int g = idx >> 9, kp = idx & 511;
        uint32_t hw, lw;
        bsplit(rowbuf[g * S_ + 2 * kp], rowbuf[g * S_ + 2 * kp + 1], hw, lw);
        const size_t w = base2 + (size_t)g * (S_ * S_ / 2) + kp;
        ((uint32_t*)g_ah)[w] = hw;
        ((uint32_t*)g_al)[w] = lw;
    }
}

// ---------------------------------------------------------------------------
// K4: O = P V per (b,h). A = probs split [S,S], B = V^T split [E,S]. K=1024.
// ---------------------------------------------------------------------------
__global__ void __launch_bounds__(256, 2) k_av()
{
    extern __shared__ char sm[];
    float acc[1][8][4] = {};
    const int bh = blockIdx.z;
    const int m0 = blockIdx.y * 128;
    gemm_core<128, 64, 8, 1, 8, 4>(
        g_ah + (size_t)bh * S_ * S_, g_al + (size_t)bh * S_ * S_, S_,
        g_vth + (size_t)bh * E_ * S_, g_vtl + (size_t)bh * E_ * S_, S_,
        m0, 0, S_ / 32, sm, acc);

    const int b = bh / H_, h = bh % H_;
    const int tid = threadIdx.x;
    const int warp = tid >> 5, lane = tid & 31;
    const int wm0 = (warp % 8) * 16;
    const int g = lane >> 2, tg = lane & 3;
#pragma unroll
    for (int nt = 0; nt < 8; ++nt) {
        const int n = nt * 8 + 2 * tg;
#pragma unroll
        for (int half = 0; half < 2; ++half) {
            const int q = m0 + wm0 + g + half * 8;
            uint32_t hw, lw;
            bsplit(acc[0][nt][half * 2], acc[0][nt][half * 2 + 1], hw, lw);
            const size_t off = ((size_t)(b * S_ + q)) * D_ + h * E_ + n;
            ((uint32_t*)g_ctxh)[off >> 1] = hw;
            ((uint32_t*)g_ctxl)[off >> 1] = lw;
        }
    }
}

// ---------------------------------------------------------------------------
// K5: out = ctx Wp^T + bp.
// ---------------------------------------------------------------------------
__global__ void __launch_bounds__(256, 2) k_proj(const float* __restrict__ bp,
                                                 float* __restrict__ out)
{
    extern __shared__ char sm[];
    float acc[2][8][4] = {};
    const int m0 = blockIdx.y * 128;
    const int n0 = blockIdx.x * 128;
    gemm_core<128, 128, 4, 2, 8, 2>(g_ctxh, g_ctxl, D_, g_wph_, g_wpl_, D_,
                                    m0, n0, D_ / 32, sm, acc);

    const int tid = threadIdx.x;
    const int warp = tid >> 5, lane = tid & 31;
    const int wm0 = (warp % 4) * 32, wn0 = (warp / 4) * 64;
    const int g = lane >> 2, tg = lane & 3;
#pragma unroll
    for (int mt = 0; mt < 2; ++mt)
#pragma unroll
        for (int nt = 0; nt < 8; ++nt) {
            const int n = n0 + wn0 + nt * 8 + 2 * tg;
            const float2 bias = make_float2(bp[n], bp[n + 1]);
#pragma unroll
            for (int half = 0; half < 2; ++half) {
                const int m = m0 + wm0 + mt * 16 + g + half * 8;
                *(float2*)(out + (size_t)m * D_ + n) =
                    make_float2(acc[mt][nt][half * 2] + bias.x,
                                acc[mt][nt][half * 2 + 1] + bias.y);
            }
        }
}

// ---------------------------------------------------------------------------
// Launch
// ---------------------------------------------------------------------------
extern "C" void kernel_launch(void* const* d_in, const int* in_sizes, int n_in,
                              void* d_out, int out_size)
{
    const float* x    = (const float*)d_in[0];
    const float* Wqkv = (const float*)d_in[1];
    const float* Wl   = (const float*)d_in[2];
    const float* bl   = (const float*)d_in[3];
    const float* Ww   = (const float*)d_in[4];
    const float* bw   = (const float*)d_in[5];
    const float* Wp   = (const float*)d_in[6];
    const float* bp   = (const float*)d_in[7];
    float* out = (float*)d_out;

    const int SM_A = 2 * (2 * 128 * PITCHB + 2 * 128 * PITCHB);  // 81920
    const int SM_B = 2 * (2 * 128 * PITCHB + 2 * 64 * PITCHB);   // 61440
    const int mix_smem = (H_ * S_ + 320) * (int)sizeof(float);

    cudaFuncSetAttribute(k_qkv,  cudaFuncAttributeMaxDynamicSharedMemorySize, SM_A);
    cudaFuncSetAttribute(k_qk,   cudaFuncAttributeMaxDynamicSharedMemorySize, SM_A);
    cudaFuncSetAttribute(k_av,   cudaFuncAttributeMaxDynamicSharedMemorySize, SM_B);
    cudaFuncSetAttribute(k_proj, cudaFuncAttributeMaxDynamicSharedMemorySize, SM_A);
    cudaFuncSetAttribute(k_mix_softmax, cudaFuncAttributeMaxDynamicSharedMemorySize,
                         mix_smem);

    __nv_bfloat16 *xh, *xl, *wqh, *wql, *wph, *wpl;
    cudaGetSymbolAddress((void**)&xh,  g_xh);
    cudaGetSymbolAddress((void**)&xl,  g_xl);
    cudaGetSymbolAddress((void**)&wqh, g_wqh);
    cudaGetSymbolAddress((void**)&wql, g_wql);
    cudaGetSymbolAddress((void**)&wph, g_wph_);
    cudaGetSymbolAddress((void**)&wpl, g_wpl_);

    const int nx = B_ * S_ * D_ / 2;
    const int nq = 3 * D_ * D_ / 2;
    const int np = D_ * D_ / 2;
    k_split<<<(nx + 255) / 256, 256>>>(x, xh, xl, nx);
    k_split<<<(nq + 255) / 256, 256>>>(Wqkv, wqh, wql, nq);
    k_split<<<(np + 255) / 256, 256>>>(Wp, wph, wpl, np);

    k_qkv<<<dim3(3 * D_ / 128, (B_ * S_) / 128), 256, SM_A>>>();
    k_vtrans<<<dim3(S_ / 64, B_ * H_), 256>>>();
    k_qk<<<dim3(S_ / 128, S_ / 128, B_ * H_), 256, SM_A>>>();
    k_mix_softmax<<<B_ * S_, 256, mix_smem>>>(Wl, bl, Ww, bw);
    k_av<<<dim3(1, S_ / 128, B_ * H_), 256, SM_B>>>();
    k_proj<<<dim3(D_ / 128, (B_ * S_) / 128), 256, SM_A>>>(bp, out);
}

// round 14
// speedup vs baseline: 2.2341x; 1.0376x over previous
#include <cuda_runtime.h>
#include <cuda_bf16.h>
#include <cstdint>

#define B_ 4
#define S_ 1024
#define D_ 768
#define H_ 12
#define E_ 64

// ---------------------------------------------------------------------------
// Persistent device scratch
// ---------------------------------------------------------------------------
__device__ __align__(16) __nv_bfloat16 g_xh[B_ * S_ * D_];
__device__ __align__(16) __nv_bfloat16 g_xl[B_ * S_ * D_];
__device__ __align__(16) __nv_bfloat16 g_wqh[3 * D_ * D_];
__device__ __align__(16) __nv_bfloat16 g_wql[3 * D_ * D_];
__device__ __align__(16) __nv_bfloat16 g_wph_[D_ * D_];
__device__ __align__(16) __nv_bfloat16 g_wpl_[D_ * D_];
__device__ __align__(16) __nv_bfloat16 g_qh[B_ * H_ * S_ * E_];
__device__ __align__(16) __nv_bfloat16 g_ql[B_ * H_ * S_ * E_];
__device__ __align__(16) __nv_bfloat16 g_kh[B_ * H_ * S_ * E_];
__device__ __align__(16) __nv_bfloat16 g_kl[B_ * H_ * S_ * E_];
__device__ __align__(16) float         g_v [B_ * H_ * S_ * E_];
__device__ __align__(16) __nv_bfloat16 g_vth[B_ * H_ * E_ * S_]; // [b,h,e,s]
__device__ __align__(16) __nv_bfloat16 g_vtl[B_ * H_ * E_ * S_];
__device__ __align__(16) float         g_attn[(size_t)B_ * H_ * S_ * S_];
__device__ __align__(16) __nv_bfloat16 g_ah[(size_t)B_ * H_ * S_ * S_];
__device__ __align__(16) __nv_bfloat16 g_al[(size_t)B_ * H_ * S_ * S_];
__device__ __align__(16) __nv_bfloat16 g_ctxh[B_ * S_ * D_];
__device__ __align__(16) __nv_bfloat16 g_ctxl[B_ * S_ * D_];

// ---------------------------------------------------------------------------
// Helpers
// ---------------------------------------------------------------------------
__device__ __forceinline__ void bsplit(float a, float b, uint32_t& hi, uint32_t& lo)
{
    __nv_bfloat162 h = __floats2bfloat162_rn(a, b);
    const float ha = __bfloat162float(h.x), hb = __bfloat162float(h.y);
    __nv_bfloat162 l = __floats2bfloat162_rn(a - ha, b - hb);
    hi = *reinterpret_cast<uint32_t*>(&h);
    lo = *reinterpret_cast<uint32_t*>(&l);
}

__device__ __forceinline__ void mma_bf16(float c[4], const uint32_t a[4],
                                         const uint32_t* b)
{
    asm volatile(
        "mma.sync.aligned.m16n8k16.row.col.f32.bf16.bf16.f32 "
        "{%0,%1,%2,%3}, {%4,%5,%6,%7}, {%8,%9}, {%0,%1,%2,%3};\n"
        : "+f"(c[0]), "+f"(c[1]), "+f"(c[2]), "+f"(c[3])
        : "r"(a[0]), "r"(a[1]), "r"(a[2]), "r"(a[3]), "r"(b[0]), "r"(b[1]));
}

__device__ __forceinline__ void ldsm4(uint32_t r[4], uint32_t addr)
{
    asm volatile("ldmatrix.sync.aligned.m8n8.x4.shared.b16 {%0,%1,%2,%3}, [%4];"
                 : "=r"(r[0]), "=r"(r[1]), "=r"(r[2]), "=r"(r[3]) : "r"(addr));
}

__device__ __forceinline__ void cpa16(uint32_t dst, const void* src)
{
    asm volatile("cp.async.cg.shared.global [%0], [%1], 16;" :: "r"(dst), "l"(src));
}
__device__ __forceinline__ void cp_commit()
{
    asm volatile("cp.async.commit_group;" ::: "memory");
}
template<int N> __device__ __forceinline__ void cp_wait()
{
    asm volatile("cp.async.wait_group %0;" :: "n"(N) : "memory");
}

// packed f32x2 (Blackwell dual-fp32 pipe; PTX-only, not 'a'-gated)
__device__ __forceinline__ uint64_t pk2(float x, float y)
{
    uint64_t d;
    asm("mov.b64 %0, {%1, %2};" : "=l"(d) : "f"(x), "f"(y));
    return d;
}
__device__ __forceinline__ float2 upk2(uint64_t d)
{
    float2 v;
    asm("mov.b64 {%0, %1}, %2;" : "=f"(v.x), "=f"(v.y) : "l"(d));
    return v;
}
#define FMA2(d, a, b, c) \
    asm("fma.rn.f32x2 %0, %1, %2, %3;" : "=l"(d) : "l"(a), "l"(b), "l"(c))

// ---------------------------------------------------------------------------
// bf16x3 GEMM core (unchanged from R13)
// ---------------------------------------------------------------------------
#define PITCHB 80

template<int BM, int BN, int WARPS_M, int MT, int NTT, int NTG>
__device__ __forceinline__ void gemm_core(
    const __nv_bfloat16* __restrict__ Ahg, const __nv_bfloat16* __restrict__ Alg,
    int lda,
    const __nv_bfloat16* __restrict__ Bhg, const __nv_bfloat16* __restrict__ Blg,
    int ldb,
    int m0, int n0, int NC, char* sm, float acc[MT][NTT][4])
{
    constexpr int A_T = BM * PITCHB;
    constexpr int B_T = BN * PITCHB;
    constexpr int STAGE = 2 * A_T + 2 * B_T;

    const int tid = threadIdx.x;
    const int warp = tid >> 5, lane = tid & 31;
    const int wm0 = (warp % WARPS_M) * (MT * 16);
    const int wn0 = (warp / WARPS_M) * (NTT * 8);
    const uint32_t sbase = (uint32_t)__cvta_generic_to_shared(sm);

    Ahg += (size_t)m0 * lda;  Alg += (size_t)m0 * lda;
    Bhg += (size_t)n0 * ldb;  Blg += (size_t)n0 * ldb;

    auto load_tile = [&](uint32_t doff, const __nv_bfloat16* src, int ld,
                         int rows, int kc) {
        for (int i = tid; i < rows * 4; i += 256) {
            const int r = i >> 2, cc = i & 3;
            cpa16(sbase + doff + r * PITCHB + cc * 16,
                  src + (size_t)r * ld + kc * 32 + cc * 8);
        }
    };
    auto load_stage = [&](int st, int kc) {
        const uint32_t o = st * STAGE;
        load_tile(o,               Ahg, lda, BM, kc);
        load_tile(o + A_T,         Alg, lda, BM, kc);
        load_tile(o + 2 * A_T,     Bhg, ldb, BN, kc);
        load_tile(o + 2 * A_T + B_T, Blg, ldb, BN, kc);
        cp_commit();
    };

    const int a_row = (lane & 7) + ((lane >> 3) & 1) * 8;
    const int a_col = ((lane >> 4) & 1) * 16;
    const int b_row = (lane & 7) + ((lane >> 4) & 1) * 8;
    const int b_col = ((lane >> 3) & 1) * 16;

    auto compute = [&](int st) {
        const uint32_t o = sbase + st * STAGE;
#pragma unroll
        for (int ks = 0; ks < 2; ++ks) {
            uint32_t ah[MT][4], al[MT][4];
#pragma unroll
            for (int mt = 0; mt < MT; ++mt) {
                const uint32_t ra =
                    o + (wm0 + mt * 16 + a_row) * PITCHB + ks * 32 + a_col;
                ldsm4(ah[mt], ra);
                ldsm4(al[mt], ra + A_T);
            }
#pragma unroll
            for (int g0 = 0; g0 < NTT / 2; g0 += NTG) {
                uint32_t bh[NTG][4], bl[NTG][4];
#pragma unroll
                for (int j = 0; j < NTG; ++j) {
                    const uint32_t rb = o + 2 * A_T +
                        (wn0 + (g0 + j) * 16 + b_row) * PITCHB + ks * 32 + b_col;
                    ldsm4(bh[j], rb);
                    ldsm4(bl[j], rb + B_T);
                }
#pragma unroll
                for (int mt = 0; mt < MT; ++mt)
#pragma unroll
                    for (int j = 0; j < NTG; ++j) {
                        mma_bf16(acc[mt][2 * (g0 + j)],     ah[mt], bh[j]);
                        mma_bf16(acc[mt][2 * (g0 + j) + 1], ah[mt], bh[j] + 2);
                    }
#pragma unroll
                for (int mt = 0; mt < MT; ++mt)
#pragma unroll
                    for (int j = 0; j < NTG; ++j) {
                        mma_bf16(acc[mt][2 * (g0 + j)],     ah[mt], bl[j]);
                        mma_bf16(acc[mt][2 * (g0 + j) + 1], ah[mt], bl[j] + 2);
                    }
#pragma unroll
                for (int mt = 0; mt < MT; ++mt)
#pragma unroll
                    for (int j = 0; j < NTG; ++j) {
                        mma_bf16(acc[mt][2 * (g0 + j)],     al[mt], bh[j]);
                        mma_bf16(acc[mt][2 * (g0 + j) + 1], al[mt], bh[j] + 2);
                    }
            }
        }
    };

    load_stage(0, 0);
    for (int c = 0; c < NC; ++c) {
        cp_wait<0>();
        __syncthreads();
        if (c + 1 < NC) load_stage((c + 1) & 1, c + 1);
        compute(c & 1);
    }
}

// ---------------------------------------------------------------------------
// Pre-pass: fp32 -> bf16 hi/lo split
// ---------------------------------------------------------------------------
__global__ void k_split(const float* __restrict__ src, __nv_bfloat16* __restrict__ h,
                        __nv_bfloat16* __restrict__ l, int npairs)
{
    const int i = blockIdx.x * blockDim.x + threadIdx.x;
    if (i < npairs) {
        const float2 v = ((const float2*)src)[i];
        uint32_t hw, lw;
        bsplit(v.x, v.y, hw, lw);
        ((uint32_t*)h)[i] = hw;
        ((uint32_t*)l)[i] = lw;
    }
}

__global__ void __launch_bounds__(256) k_vtrans()
{
    __shared__ float t[64][65];
    const int s0 = blockIdx.x * 64;
    const int bh = blockIdx.y;
    const int tid = threadIdx.x;
    for (int idx = tid; idx < 4096; idx += 256) {
        const int e = idx & 63, r = idx >> 6;
        t[e][r] = g_v[((size_t)bh * 1024 + s0 + r) * 64 + e];
    }
    __syncthreads();
    for (int idx = tid; idx < 2048; idx += 256) {
        const int e = idx >> 5, sp = idx & 31;
        uint32_t hw, lw;
        bsplit(t[e][2 * sp], t[e][2 * sp + 1], hw, lw);
        const size_t w = ((size_t)(bh * 64 + e) * 1024 + s0) / 2 + sp;
        ((uint32_t*)g_vth)[w] = hw;
        ((uint32_t*)g_vtl)[w] = lw;
    }
}

// ---------------------------------------------------------------------------
// K1: QKV
// ---------------------------------------------------------------------------
__global__ void __launch_bounds__(256, 2) k_qkv()
{
    extern __shared__ char sm[];
    float acc[2][8][4] = {};
    const int m0 = blockIdx.y * 128;
    const int n0 = blockIdx.x * 128;
    gemm_core<128, 128, 4, 2, 8, 2>(g_xh, g_xl, D_, g_wqh, g_wql, D_,
                                    m0, n0, D_ / 32, sm, acc);

    const int tid = threadIdx.x;
    const int warp = tid >> 5, lane = tid & 31;
    const int wm0 = (warp % 4) * 32, wn0 = (warp / 4) * 64;
    const int g = lane >> 2, tg = lane & 3;
    const int t = n0 / D_;
    const int rem0 = n0 % D_;
    __nv_bfloat16* ph = (t == 0) ? g_qh : g_kh;
    __nv_bfloat16* pl = (t == 0) ? g_ql : g_kl;
#pragma unroll
    for (int mt = 0; mt < 2; ++mt)
#pragma unroll
        for (int nt = 0; nt < 8; ++nt) {
            const int rem = rem0 + wn0 + nt * 8 + 2 * tg;
            const int h = rem >> 6, e = rem & 63;
#pragma unroll
            for (int half = 0; half < 2; ++half) {
                const int m = m0 + wm0 + mt * 16 + g + half * 8;
                const int b = m >> 10, s = m & 1023;
                const size_t off = (((size_t)(b * H_ + h)) * S_ + s) * E_ + e;
                const float f0 = acc[mt][nt][half * 2];
                const float f1 = acc[mt][nt][half * 2 + 1];
                if (t == 2) {
                    *(float2*)(g_v + off) = make_float2(f0, f1);
                } else {
                    uint32_t hw, lw;
                    bsplit(f0, f1, hw, lw);
                    ((uint32_t*)ph)[off >> 1] = hw;
                    ((uint32_t*)pl)[off >> 1] = lw;
                }
            }
        }
}

// ---------------------------------------------------------------------------
// K2: logits = Q K^T per (b,h)
// ---------------------------------------------------------------------------
__global__ void __launch_bounds__(256, 2) k_qk()
{
    extern __shared__ char sm[];
    float acc[2][8][4] = {};
    const int bh = blockIdx.z;
    const int m0 = blockIdx.y * 128;
    const int n0 = blockIdx.x * 128;
    gemm_core<128, 128, 4, 2, 8, 2>(
        g_qh + (size_t)bh * S_ * E_, g_ql + (size_t)bh * S_ * E_, E_,
        g_kh + (size_t)bh * S_ * E_, g_kl + (size_t)bh * S_ * E_, E_,
        m0, n0, E_ / 32, sm, acc);

    float* C = g_attn + (size_t)bh * S_ * S_;
    const int tid = threadIdx.x;
    const int warp = tid >> 5, lane = tid & 31;
    const int wm0 = (warp % 4) * 32, wn0 = (warp / 4) * 64;
    const int g = lane >> 2, tg = lane & 3;
#pragma unroll
    for (int mt = 0; mt < 2; ++mt)
#pragma unroll
        for (int nt = 0; nt < 8; ++nt) {
            const int n = n0 + wn0 + nt * 8 + 2 * tg;
#pragma unroll
            for (int half = 0; half < 2; ++half) {
                const int m = m0 + wm0 + mt * 16 + g + half * 8;
                *(float2*)(C + (size_t)m * S_ + n) =
                    make_float2(acc[mt][nt][half * 2], acc[mt][nt][half * 2 + 1]);
            }
        }
}

// ---------------------------------------------------------------------------
// K3: mix1 -> softmax -> mix2 (f32x2-packed mixes, folded normalization)
// ---------------------------------------------------------------------------
__device__ __forceinline__ float fast_exp(float x)
{
    const float y = x * 1.4426950408889634f;
    const float r = rintf(y);
    const float f = y - r;
    float p = 1.5403530e-4f;
    p = fmaf(p, f, 1.3333558e-3f);
    p = fmaf(p, f, 9.6181291e-3f);
    p = fmaf(p, f, 5.5504109e-2f);
    p = fmaf(p, f, 2.4022651e-1f);
    p = fmaf(p, f, 6.9314718e-1f);
    p = fmaf(p, f, 1.0f);
    const int ri = (int)fmaxf(r, -126.0f);
    return __int_as_float(__float_as_int(p) + (ri << 23));
}

// smem float layout:
//   [0,12288)      rowbuf [12][1024]
//   [12288,12576)  wWl2  (144 x float2, duplicated Wl)
//   [12576,12864)  wWw2  (144 x float2, Ww / Z_h, duplicated)
//   [12864,12876)  wbl
//   [12876,12888)  wbw
//   [12888,13032)  wraw  (Ww)
//   [13032,13044)  sinv  (1/Z per head)
__global__ void __launch_bounds__(256) k_mix_softmax(const float* __restrict__ Wl,
                                                     const float* __restrict__ bl,
                                                     const float* __restrict__ Ww,
                                                     const float* __restrict__ bw)
{
    extern __shared__ __align__(16) float smf[];
    float* rowbuf = smf;
    float2* wWl2 = (float2*)(smf + 12288);
    float2* wWw2 = (float2*)(smf + 12576);
    float* wbl  = smf + 12864;
    float* wbw  = smf + 12876;
    float* wraw = smf + 12888;
    float* sinv = smf + 13032;
    const uint64_t* wWl2u = (const uint64_t*)wWl2;
    const uint64_t* wWw2u = (const uint64_t*)wWw2;

    const int tid = threadIdx.x;
    const int bq = blockIdx.x;
    const int b = bq >> 10, q = bq & 1023;

    for (int i = tid; i < 144; i += 256) {
        const float wl = Wl[i];
        wWl2[i] = make_float2(wl, wl);
        wraw[i] = Ww[i];
    }
    if (tid < 12) { wbl[tid] = bl[tid]; wbw[tid] = bw[tid]; }

    const size_t base = ((size_t)b * H_) * S_ * S_ + (size_t)q * S_;
    for (int h = 0; h < H_; ++h) {
        const float4* src = (const float4*)(g_attn + base + (size_t)h * S_ * S_);
        ((float4*)(rowbuf + h * S_))[tid] = src[tid];
    }
    __syncthreads();

    // mix1, packed over column pairs
    for (int kp = tid; kp < S_ / 2; kp += 256) {
        uint64_t l2[H_];
#pragma unroll
        for (int h = 0; h < H_; ++h) {
            const float2 v = *(const float2*)(rowbuf + h * S_ + 2 * kp);
            l2[h] = pk2(v.x, v.y);
        }
        uint64_t m2[H_];
#pragma unroll
        for (int g = 0; g < H_; ++g) {
            uint64_t a = pk2(wbl[g], wbl[g]);
#pragma unroll
            for (int h = 0; h < H_; ++h) FMA2(a, wWl2u[g * H_ + h], l2[h], a);
            m2[g] = a;
        }
#pragma unroll
        for (int g = 0; g < H_; ++g)
            *(float2*)(rowbuf + g * S_ + 2 * kp) = upk2(m2[g]);
    }
    __syncthreads();

    // softmax numerators + per-row 1/Z (no normalization pass)
    const int warp = tid >> 5, lane = tid & 31;
    for (int row = warp; row < H_; row += 8) {
        float* r = rowbuf + row * S_;
        float mx = -1e30f;
        for (int k = lane; k < S_; k += 32) mx = fmaxf(mx, r[k]);
#pragma unroll
        for (int o = 16; o; o >>= 1) mx = fmaxf(mx, __shfl_xor_sync(0xffffffffu, mx, o));
        float s = 0.f;
        for (int k = lane; k < S_; k += 32) {
            const float e = fast_exp(r[k] - mx);
            r[k] = e;
            s += e;
        }
#pragma unroll
        for (int o = 16; o; o >>= 1) s += __shfl_xor_sync(0xffffffffu, s, o);
        if (lane == 0) sinv[row] = 1.0f / s;
    }
    __syncthreads();

    // fold 1/Z into mix2 weights
    if (tid < 144) {
        const float w = wraw[tid] * sinv[tid % H_];
        wWw2[tid] = make_float2(w, w);
    }
    __syncthreads();

    // mix2, packed; writes final (normalized + bias) values
    for (int kp = tid; kp < S_ / 2; kp += 256) {
        uint64_t e2[H_];
#pragma unroll
        for (int h = 0; h < H_; ++h) {
            const float2 v = *(const float2*)(rowbuf + h * S_ + 2 * kp);
            e2[h] = pk2(v.x, v.y);
        }
        uint64_t o2[H_];
#pragma unroll
        for (int g = 0; g < H_; ++g) {
            uint64_t a = pk2(wbw[g], wbw[g]);
#pragma unroll
            for (int h = 0; h < H_; ++h) FMA2(a, wWw2u[g * H_ + h], e2[h], a);
            o2[g] = a;
        }
#pragma unroll
        for (int g = 0; g < H_; ++g)
            *(float2*)(rowbuf + g * S_ + 2 * kp) = upk2(o2[g]);
    }
    __syncthreads();

    // split-store to g_ah / g_al
    const size_t base2 = base / 2;
    for (int idx = tid; idx < H_ * (S_ / 2); idx += 256) {
        const int g = idx >> 9, kp = idx & 511;
        uint32_t hw, lw;
        bsplit(rowbuf[g * S_ + 2 * kp], rowbuf[g * S_ + 2 * kp + 1], hw, lw);
        const size_t w = base2 + (size_t)g * (S_ * S_ / 2) + kp;
        ((uint32_t*)g_ah)[w] = hw;
        ((uint32_t*)g_al)[w] = lw;
    }
}

// ---------------------------------------------------------------------------
// K4: O = P V per (b,h)
// ---------------------------------------------------------------------------
__global__ void __launch_bounds__(256, 2) k_av()
{
    extern __shared__ char sm[];
    float acc[1][8][4] = {};
    const int bh = blockIdx.z;
    const int m0 = blockIdx.y * 128;
    gemm_core<128, 64, 8, 1, 8, 4>(
        g_ah + (size_t)bh * S_ * S_, g_al + (size_t)bh * S_ * S_, S_,
        g_vth + (size_t)bh * E_ * S_, g_vtl + (size_t)bh * E_ * S_, S_,
        m0, 0, S_ / 32, sm, acc);

    const int b = bh / H_, h = bh % H_;
    const int tid = threadIdx.x;
    const int warp = tid >> 5, lane = tid & 31;
    const int wm0 = (warp % 8) * 16;
    const int g = lane >> 2, tg = lane & 3;
#pragma unroll
    for (int nt = 0; nt < 8; ++nt) {
        const int n = nt * 8 + 2 * tg;
#pragma unroll
        for (int half = 0; half < 2; ++half) {
            const int q = m0 + wm0 + g + half * 8;
            uint32_t hw, lw;
            bsplit(acc[0][nt][half * 2], acc[0][nt][half * 2 + 1], hw, lw);
            const size_t off = ((size_t)(b * S_ + q)) * D_ + h * E_ + n;
            ((uint32_t*)g_ctxh)[off >> 1] = hw;
            ((uint32_t*)g_ctxl)[off >> 1] = lw;
        }
    }
}

// ---------------------------------------------------------------------------
// K5: out = ctx Wp^T + bp
// ---------------------------------------------------------------------------
__global__ void __launch_bounds__(256, 2) k_proj(const float* __restrict__ bp,
                                                 float* __restrict__ out)
{
    extern __shared__ char sm[];
    float acc[2][8][4] = {};
    const int m0 = blockIdx.y * 128;
    const int n0 = blockIdx.x * 128;
    gemm_core<128, 128, 4, 2, 8, 2>(g_ctxh, g_ctxl, D_, g_wph_, g_wpl_, D_,
                                    m0, n0, D_ / 32, sm, acc);

    const int tid = threadIdx.x;
    const int warp = tid >> 5, lane = tid & 31;
    const int wm0 = (warp % 4) * 32, wn0 = (warp / 4) * 64;
    const int g = lane >> 2, tg = lane & 3;
#pragma unroll
    for (int mt = 0; mt < 2; ++mt)
#pragma unroll
        for (int nt = 0; nt < 8; ++nt) {
            const int n = n0 + wn0 + nt * 8 + 2 * tg;
            const float2 bias = make_float2(bp[n], bp[n + 1]);
#pragma unroll
            for (int half = 0; half < 2; ++half) {
                const int m = m0 + wm0 + mt * 16 + g + half * 8;
                *(float2*)(out + (size_t)m * D_ + n) =
                    make_float2(acc[mt][nt][half * 2] + bias.x,
                                acc[mt][nt][half * 2 + 1] + bias.y);
            }
        }
}

// ---------------------------------------------------------------------------
// Launch
// ---------------------------------------------------------------------------
extern "C" void kernel_launch(void* const* d_in, const int* in_sizes, int n_in,
                              void* d_out, int out_size)
{
    const float* x    = (const float*)d_in[0];
    const float* Wqkv = (const float*)d_in[1];
    const float* Wl   = (const float*)d_in[2];
    const float* bl   = (const float*)d_in[3];
    const float* Ww   = (const float*)d_in[4];
    const float* bw   = (const float*)d_in[5];
    const float* Wp   = (const float*)d_in[6];
    const float* bp   = (const float*)d_in[7];
    float* out = (float*)d_out;

    const int SM_A = 2 * (2 * 128 * PITCHB + 2 * 128 * PITCHB);  // 81920
    const int SM_B = 2 * (2 * 128 * PITCHB + 2 * 64 * PITCHB);   // 61440
    const int mix_smem = 13056 * (int)sizeof(float);             // 52224

    cudaFuncSetAttribute(k_qkv,  cudaFuncAttributeMaxDynamicSharedMemorySize, SM_A);
    cudaFuncSetAttribute(k_qk,   cudaFuncAttributeMaxDynamicSharedMemorySize, SM_A);
    cudaFuncSetAttribute(k_av,   cudaFuncAttributeMaxDynamicSharedMemorySize, SM_B);
    cudaFuncSetAttribute(k_proj, cudaFuncAttributeMaxDynamicSharedMemorySize, SM_A);
    cudaFuncSetAttribute(k_mix_softmax, cudaFuncAttributeMaxDynamicSharedMemorySize,
                         mix_smem);

    __nv_bfloat16 *xh, *xl, *wqh, *wql, *wph, *wpl;
    cudaGetSymbolAddress((void**)&xh,  g_xh);
    cudaGetSymbolAddress((void**)&xl,  g_xl);
    cudaGetSymbolAddress((void**)&wqh, g_wqh);
    cudaGetSymbolAddress((void**)&wql, g_wql);
    cudaGetSymbolAddress((void**)&wph, g_wph_);
    cudaGetSymbolAddress((void**)&wpl, g_wpl_);

    const int nx = B_ * S_ * D_ / 2;
    const int nq = 3 * D_ * D_ / 2;
    const int np = D_ * D_ / 2;
    k_split<<<(nx + 255) / 256, 256>>>(x, xh, xl, nx);
    k_split<<<(nq + 255) / 256, 256>>>(Wqkv, wqh, wql, nq);
    k_split<<<(np + 255) / 256, 256>>>(Wp, wph, wpl, np);

    k_qkv<<<dim3(3 * D_ / 128, (B_ * S_) / 128), 256, SM_A>>>();
    k_vtrans<<<dim3(S_ / 64, B_ * H_), 256>>>();
    k_qk<<<dim3(S_ / 128, S_ / 128, B_ * H_), 256, SM_A>>>();
    k_mix_softmax<<<B_ * S_, 256, mix_smem>>>(Wl, bl, Ww, bw);
    k_av<<<dim3(1, S_ / 128, B_ * H_), 256, SM_B>>>();
    k_proj<<<dim3(D_ / 128, (B_ * S_) / 128), 256, SM_A>>>(bp, out);
}